// round 7
// baseline (speedup 1.0000x reference)
#include <cuda_runtime.h>
#include <cuda_fp16.h>
#include <math.h>
#include <stdint.h>

#define HDIM 1024
#define IDIM 2752
#define NE   8
#define NT   4096
#define NROUTED (2*NT)
#define NRP  9216
#define SHB  9216
#define NEP  (NRP + NT)
#define MAXTILES 72

// ---------------- scratch ----------------
__device__ int   g_counts[NE];
__device__ int   g_offp[NE];
__device__ int   g_cursor[NE];
__device__ int   g_tile_e[MAXTILES];
__device__ int   g_tile_m[MAXTILES];
__device__ int   g_topk_idx[NROUTED];
__device__ float g_topk_w[NROUTED];
__device__ int   g_perm[NRP];
__device__ float g_wgt[NRP];
__device__ int   g_entry_of[NROUTED];

__device__ __half g_x16[(size_t)NT * HDIM];
__device__ __half g_wg[(size_t)NE * IDIM * HDIM];
__device__ __half g_wu[(size_t)NE * IDIM * HDIM];
__device__ __half g_wd[(size_t)NE * HDIM * IDIM];
__device__ __half g_sg[(size_t)IDIM * HDIM];
__device__ __half g_su[(size_t)IDIM * HDIM];
__device__ __half g_sd[(size_t)HDIM * IDIM];
__device__ __half g_hm[(size_t)NEP * IDIM];
__device__ float  g_eo[(size_t)NEP * HDIM];

// ---------------- helpers ----------------
__device__ __forceinline__ uint32_t smem_u32(const void* p) {
    uint32_t a;
    asm("{ .reg .u64 t; cvta.to.shared.u64 t, %1; cvt.u32.u64 %0, t; }"
        : "=r"(a) : "l"(p));
    return a;
}
__device__ __forceinline__ void ldsm4(uint32_t* r, uint32_t a) {
    asm volatile("ldmatrix.sync.aligned.m8n8.x4.shared.b16 {%0,%1,%2,%3}, [%4];"
                 : "=r"(r[0]), "=r"(r[1]), "=r"(r[2]), "=r"(r[3]) : "r"(a));
}
__device__ __forceinline__ void mma16816(float* c, const uint32_t* a,
                                         uint32_t b0, uint32_t b1) {
    asm volatile(
        "mma.sync.aligned.m16n8k16.row.col.f32.f16.f16.f32 "
        "{%0,%1,%2,%3}, {%4,%5,%6,%7}, {%8,%9}, {%0,%1,%2,%3};"
        : "+f"(c[0]), "+f"(c[1]), "+f"(c[2]), "+f"(c[3])
        : "r"(a[0]), "r"(a[1]), "r"(a[2]), "r"(a[3]), "r"(b0), "r"(b1));
}
__device__ __forceinline__ void cpasync16(uint32_t dst, const void* src) {
    asm volatile("cp.async.cg.shared.global [%0], [%1], 16;" :: "r"(dst), "l"(src));
}
#define CP_COMMIT() asm volatile("cp.async.commit_group;" ::: "memory")
#define CP_WAIT1()  asm volatile("cp.async.wait_group 1;" ::: "memory")
#define CP_WAIT0()  asm volatile("cp.async.wait_group 0;" ::: "memory")

__device__ __forceinline__ uint32_t pack2h(__half a, __half b) {
    return ((uint32_t)__half_as_ushort(b) << 16) | __half_as_ushort(a);
}

// ---------------- small kernels ----------------
__global__ void init_kernel() {
    int i = threadIdx.x;
    if (i < NE) g_counts[i] = 0;
}

// float -> fp16
__global__ void conv_f16_kernel(const float* __restrict__ src,
                                __half* __restrict__ h, int n4) {
    int i = blockIdx.x * blockDim.x + threadIdx.x;
    if (i >= n4) return;
    float4 v = ((const float4*)src)[i];
    uint2 ph;
    ph.x = pack2h(__float2half_rn(v.x), __float2half_rn(v.y));
    ph.y = pack2h(__float2half_rn(v.z), __float2half_rn(v.w));
    ((uint2*)h)[i] = ph;
}

__global__ void gate_kernel(const float* __restrict__ x,
                            const float* __restrict__ gw) {
    int warp = (blockIdx.x * blockDim.x + threadIdx.x) >> 5;
    int lane = threadIdx.x & 31;
    if (warp >= NT) return;
    const float4* x4 = (const float4*)(x + (size_t)warp * HDIM);
    const float4* gw4 = (const float4*)gw;
    float acc[NE];
#pragma unroll
    for (int e = 0; e < NE; e++) acc[e] = 0.f;
    for (int h4 = lane; h4 < HDIM / 4; h4 += 32) {
        float4 xv = x4[h4];
#pragma unroll
        for (int e = 0; e < NE; e++) {
            float4 g = gw4[e * (HDIM / 4) + h4];
            acc[e] += xv.x * g.x + xv.y * g.y + xv.z * g.z + xv.w * g.w;
        }
    }
#pragma unroll
    for (int e = 0; e < NE; e++)
#pragma unroll
        for (int off = 16; off > 0; off >>= 1)
            acc[e] += __shfl_down_sync(0xffffffffu, acc[e], off);
    if (lane == 0) {
        float mx = acc[0];
#pragma unroll
        for (int e = 1; e < NE; e++) mx = fmaxf(mx, acc[e]);
        float p[NE], s = 0.f;
#pragma unroll
        for (int e = 0; e < NE; e++) { p[e] = expf(acc[e] - mx); s += p[e]; }
        float inv = 1.f / s;
#pragma unroll
        for (int e = 0; e < NE; e++) p[e] *= inv;
        int i1 = 0; float p1 = p[0];
#pragma unroll
        for (int e = 1; e < NE; e++) if (p[e] > p1) { p1 = p[e]; i1 = e; }
        int i2 = -1; float p2 = -1.f;
#pragma unroll
        for (int e = 0; e < NE; e++) {
            if (e == i1) continue;
            if (p[e] > p2) { p2 = p[e]; i2 = e; }
        }
        float rn = 1.f / (p1 + p2 + 1e-20f);
        g_topk_idx[2 * warp + 0] = i1;
        g_topk_idx[2 * warp + 1] = i2;
        g_topk_w[2 * warp + 0] = p1 * rn;
        g_topk_w[2 * warp + 1] = p2 * rn;
        atomicAdd(&g_counts[i1], 1);
        atomicAdd(&g_counts[i2], 1);
    }
}

__global__ void scan_kernel() {
    if (threadIdx.x == 0) {
        int s = 0, t = 0;
        for (int e = 0; e < NE; e++) {
            g_offp[e] = s;
            g_cursor[e] = s;
            int c = g_counts[e];
            int nt = (c + 127) >> 7;
            for (int m = 0; m < nt; m++) { g_tile_e[t] = e; g_tile_m[t] = m << 7; t++; }
            s += (c + 127) & ~127;
        }
        for (; t < MAXTILES; t++) g_tile_e[t] = -1;
    }
}

__global__ void scatter_kernel() {
    int i = blockIdx.x * blockDim.x + threadIdx.x;
    if (i >= NROUTED) return;
    int t = i >> 1;
    int e = g_topk_idx[i];
    int pos = atomicAdd(&g_cursor[e], 1);
    g_perm[pos] = t;
    g_wgt[pos] = g_topk_w[i];
    g_entry_of[i] = pos;
}

// ---------------- gate+up MMA GEMM ----------------
// block 128x128 (x2 outputs), 8 warps (64x32 warp tiles), BK=64, single-pass fp16
// 3-stage cp.async pipeline, one bar/stage; smem-staged coalesced epilogue
#define GU_PART  16384
#define GU_STAGE (3 * GU_PART)   // A, G, U
#define GU_SMEM  (3 * GU_STAGE)  // 144KB

__global__ __launch_bounds__(256, 1) void gateup_mma() {
    extern __shared__ char sm[];
    uint32_t sb = smem_u32(sm);
    int tid = threadIdx.x, wid = tid >> 5, lane = tid & 31;

    int y = blockIdx.y;
    int e, m0, base;
    bool is_shared;
    if (y >= MAXTILES) {
        is_shared = true; m0 = (y - MAXTILES) << 7; base = SHB;
    } else {
        e = g_tile_e[y];
        if (e < 0) return;
        is_shared = false; m0 = g_tile_m[y]; base = g_offp[e];
    }
    int n0 = blockIdx.x * 128;
    int N = IDIM - n0; if (N > 128) N = 128;

    const __half* WG = is_shared ? g_sg : g_wg + (size_t)e * IDIM * HDIM;
    const __half* WU = is_shared ? g_su : g_wu + (size_t)e * IDIM * HDIM;

    int lrow = tid >> 1, kb0 = (tid & 1) * 4;
    uint32_t swo[4];
#pragma unroll
    for (int j = 0; j < 4; j++)
        swo[j] = lrow * 128 + (((kb0 + j) ^ (lrow & 7)) << 4);
    int tok = is_shared ? (m0 + lrow) : g_perm[base + m0 + lrow];
    const __half* pA = g_x16 + (size_t)tok * HDIM + kb0 * 8;
    int nr = n0 + lrow; if (nr > IDIM - 1) nr = IDIM - 1;
    const __half* pG = WG + (size_t)nr * HDIM + kb0 * 8;
    const __half* pU = WU + (size_t)nr * HDIM + kb0 * 8;

    auto issue = [&](int s) {
        int k0 = s * 64;
        uint32_t bb = sb + (s % 3) * GU_STAGE;
#pragma unroll
        for (int j = 0; j < 4; j++) {
            cpasync16(bb + 0 * GU_PART + swo[j], pA + k0 + j * 8);
            cpasync16(bb + 1 * GU_PART + swo[j], pG + k0 + j * 8);
            cpasync16(bb + 2 * GU_PART + swo[j], pU + k0 + j * 8);
        }
    };

    int warpM = (wid & 1) * 64;
    int warpN = (wid >> 1) * 32;
    int la = lane & 15, kh = lane >> 4, x7 = la & 7;
    uint32_t rowA[4], rowB[2];
#pragma unroll
    for (int mf = 0; mf < 4; mf++) rowA[mf] = (warpM + mf * 16 + la) * 128;
#pragma unroll
    for (int s2 = 0; s2 < 2; s2++) rowB[s2] = (warpN + s2 * 16 + la) * 128;

    float aG[4][4][4], aU[4][4][4];
#pragma unroll
    for (int mf = 0; mf < 4; mf++)
#pragma unroll
        for (int nf = 0; nf < 4; nf++)
#pragma unroll
            for (int q = 0; q < 4; q++) { aG[mf][nf][q] = 0.f; aU[mf][nf][q] = 0.f; }

    issue(0); CP_COMMIT();
    issue(1); CP_COMMIT();
    const int S = 16;
    for (int s = 0; s < S; s++) {
        if (s == S - 1) CP_WAIT0(); else CP_WAIT1();
        __syncthreads();
        uint32_t bb = sb + (s % 3) * GU_STAGE;
#pragma unroll
        for (int k16 = 0; k16 < 4; k16++) {
            uint32_t ko = (uint32_t)(((k16 * 2 + kh) ^ x7) << 4);
            uint32_t A[4][4];
#pragma unroll
            for (int mf = 0; mf < 4; mf++)
                ldsm4(A[mf], bb + 0 * GU_PART + rowA[mf] + ko);
            uint32_t G[2][4], U[2][4];
#pragma unroll
            for (int s2 = 0; s2 < 2; s2++) {
                ldsm4(G[s2], bb + 1 * GU_PART + rowB[s2] + ko);
                ldsm4(U[s2], bb + 2 * GU_PART + rowB[s2] + ko);
            }
#pragma unroll
            for (int mf = 0; mf < 4; mf++)
#pragma unroll
                for (int s2 = 0; s2 < 2; s2++)
#pragma unroll
                    for (int j = 0; j < 2; j++) {
                        int nf = s2 * 2 + j;
                        mma16816(aG[mf][nf], A[mf], G[s2][j], G[s2][2 + j]);
                        mma16816(aU[mf][nf], A[mf], U[s2][j], U[s2][2 + j]);
                    }
        }
        if (s + 2 < S) { issue(s + 2); CP_COMMIT(); }
    }

    // epilogue: hmid = silu(g)*u -> fp16, staged through smem (stride 68 u32)
    __syncthreads();
    uint32_t* st32 = (uint32_t*)sm;
    int qr = lane >> 2, qc = (lane & 3) * 2;
#pragma unroll
    for (int mf = 0; mf < 4; mf++)
#pragma unroll
        for (int nf = 0; nf < 4; nf++) {
            float* cg = aG[mf][nf];
            float* cu = aU[mf][nf];
            int colp = (warpN + nf * 8 + qc) >> 1;
            int r0 = warpM + mf * 16 + qr;
            float g0 = cg[0], g1 = cg[1], g2 = cg[2], g3 = cg[3];
            float v00 = (g0 / (1.f + expf(-g0))) * cu[0];
            float v01 = (g1 / (1.f + expf(-g1))) * cu[1];
            float v10 = (g2 / (1.f + expf(-g2))) * cu[2];
            float v11 = (g3 / (1.f + expf(-g3))) * cu[3];
            st32[r0 * 68 + colp] = pack2h(__float2half_rn(v00), __float2half_rn(v01));
            st32[(r0 + 8) * 68 + colp] = pack2h(__float2half_rn(v10), __float2half_rn(v11));
        }
    __syncthreads();
    {
        int row = tid >> 1, half = tid & 1;
        size_t gbase = (size_t)(base + m0 + row) * IDIM + n0 + half * 64;
        int sbase = row * 68 + half * 32;
#pragma unroll
        for (int c4 = 0; c4 < 8; c4++) {
            if (half * 64 + c4 * 8 < N) {
                uint4 v = *(uint4*)&st32[sbase + c4 * 4];
                *(uint4*)(g_hm + gbase + c4 * 8) = v;
            }
        }
    }
}

// ---------------- down MMA GEMM ----------------
#define DN_PART  16384
#define DN_STAGE (2 * DN_PART)   // A, B
#define DN_SMEM  (3 * DN_STAGE)  // 96KB

__global__ __launch_bounds__(256, 1) void down_mma() {
    extern __shared__ char sm[];
    uint32_t sb = smem_u32(sm);
    int tid = threadIdx.x, wid = tid >> 5, lane = tid & 31;

    int y = blockIdx.y;
    int e, m0, base;
    bool is_shared;
    if (y >= MAXTILES) {
        is_shared = true; m0 = (y - MAXTILES) << 7; base = SHB;
    } else {
        e = g_tile_e[y];
        if (e < 0) return;
        is_shared = false; m0 = g_tile_m[y]; base = g_offp[e];
    }
    int n0 = blockIdx.x * 128;

    const __half* WD = is_shared ? g_sd : g_wd + (size_t)e * HDIM * IDIM;

    int lrow = tid >> 1, kb0 = (tid & 1) * 4;
    uint32_t swo[4];
#pragma unroll
    for (int j = 0; j < 4; j++)
        swo[j] = lrow * 128 + (((kb0 + j) ^ (lrow & 7)) << 4);
    const __half* pA = g_hm + (size_t)(base + m0 + lrow) * IDIM + kb0 * 8;
    const __half* pB = WD + (size_t)(n0 + lrow) * IDIM + kb0 * 8;

    auto issue = [&](int s) {
        int k0 = s * 64;
        uint32_t bb = sb + (s % 3) * DN_STAGE;
#pragma unroll
        for (int j = 0; j < 4; j++) {
            cpasync16(bb + 0 * DN_PART + swo[j], pA + k0 + j * 8);
            cpasync16(bb + 1 * DN_PART + swo[j], pB + k0 + j * 8);
        }
    };

    int warpM = (wid & 1) * 64;
    int warpN = (wid >> 1) * 32;
    int la = lane & 15, kh = lane >> 4, x7 = la & 7;
    uint32_t rowA[4], rowB[2];
#pragma unroll
    for (int mf = 0; mf < 4; mf++) rowA[mf] = (warpM + mf * 16 + la) * 128;
#pragma unroll
    for (int s2 = 0; s2 < 2; s2++) rowB[s2] = (warpN + s2 * 16 + la) * 128;

    float acc[4][4][4];
#pragma unroll
    for (int mf = 0; mf < 4; mf++)
#pragma unroll
        for (int nf = 0; nf < 4; nf++)
#pragma unroll
            for (int q = 0; q < 4; q++) acc[mf][nf][q] = 0.f;

    const int S = IDIM / 64;   // 43
    issue(0); CP_COMMIT();
    issue(1); CP_COMMIT();
    for (int s = 0; s < S; s++) {
        if (s == S - 1) CP_WAIT0(); else CP_WAIT1();
        __syncthreads();
        uint32_t bb = sb + (s % 3) * DN_STAGE;
#pragma unroll
        for (int k16 = 0; k16 < 4; k16++) {
            uint32_t ko = (uint32_t)(((k16 * 2 + kh) ^ x7) << 4);
            uint32_t A[4][4];
#pragma unroll
            for (int mf = 0; mf < 4; mf++)
                ldsm4(A[mf], bb + 0 * DN_PART + rowA[mf] + ko);
            uint32_t B[2][4];
#pragma unroll
            for (int s2 = 0; s2 < 2; s2++)
                ldsm4(B[s2], bb + 1 * DN_PART + rowB[s2] + ko);
#pragma unroll
            for (int mf = 0; mf < 4; mf++)
#pragma unroll
                for (int s2 = 0; s2 < 2; s2++)
#pragma unroll
                    for (int j = 0; j < 2; j++) {
                        int nf = s2 * 2 + j;
                        mma16816(acc[mf][nf], A[mf], B[s2][j], B[s2][2 + j]);
                    }
        }
        if (s + 2 < S) { issue(s + 2); CP_COMMIT(); }
    }

    // epilogue: scale by routing weight, stage through smem (stride 132 floats)
    __syncthreads();
    float* stf = (float*)sm;
    int qr = lane >> 2, qc = (lane & 3) * 2;
#pragma unroll
    for (int mf = 0; mf < 4; mf++) {
        int r0 = warpM + mf * 16 + qr;
        float w0 = is_shared ? 1.f : g_wgt[base + m0 + r0];
        float w1 = is_shared ? 1.f : g_wgt[base + m0 + r0 + 8];
#pragma unroll
        for (int nf = 0; nf < 4; nf++) {
            int col = warpN + nf * 8 + qc;
            float* c = acc[mf][nf];
            *(float2*)&stf[r0 * 132 + col] = make_float2(c[0] * w0, c[1] * w0);
            *(float2*)&stf[(r0 + 8) * 132 + col] = make_float2(c[2] * w1, c[3] * w1);
        }
    }
    __syncthreads();
    {
        int row = tid >> 1, half = tid & 1;
        float* dst = g_eo + (size_t)(base + m0 + row) * HDIM + n0 + half * 64;
        int src = row * 132 + half * 64;
#pragma unroll
        for (int c4 = 0; c4 < 16; c4++)
            *(uint4*)(dst + c4 * 4) = *(uint4*)&stf[src + c4 * 4];
    }
}

// ---------------- combine ----------------
__global__ void combine_kernel(float* __restrict__ out) {
    int idx = blockIdx.x * blockDim.x + threadIdx.x;
    const int HC = HDIM / 4;
    if (idx >= NT * HC) return;
    int t = idx / HC;
    int c = idx - t * HC;
    const float4* eo4 = (const float4*)g_eo;
    int e1 = g_entry_of[2 * t + 0];
    int e2 = g_entry_of[2 * t + 1];
    float4 a = eo4[(size_t)e1 * HC + c];
    float4 b = eo4[(size_t)e2 * HC + c];
    float4 s = eo4[(size_t)(SHB + t) * HC + c];
    float4 r;
    r.x = a.x + b.x + s.x;
    r.y = a.y + b.y + s.y;
    r.z = a.z + b.z + s.z;
    r.w = a.w + b.w + s.w;
    ((float4*)out)[idx] = r;
}

// ---------------- launch ----------------
extern "C" void kernel_launch(void* const* d_in, const int* in_sizes, int n_in,
                              void* d_out, int out_size) {
    const float* x       = (const float*)d_in[0];
    const float* gate_w  = (const float*)d_in[1];
    const float* w_gate  = (const float*)d_in[2];
    const float* w_up    = (const float*)d_in[3];
    const float* w_down  = (const float*)d_in[4];
    const float* ws_gate = (const float*)d_in[5];
    const float* ws_up   = (const float*)d_in[6];
    const float* ws_down = (const float*)d_in[7];
    float* out = (float*)d_out;

    cudaFuncSetAttribute(gateup_mma, cudaFuncAttributeMaxDynamicSharedMemorySize, GU_SMEM);
    cudaFuncSetAttribute(down_mma,   cudaFuncAttributeMaxDynamicSharedMemorySize, DN_SMEM);

    __half *x16, *wg, *wu, *wd, *sg, *su, *sd;
    cudaGetSymbolAddress((void**)&x16, g_x16);
    cudaGetSymbolAddress((void**)&wg, g_wg); cudaGetSymbolAddress((void**)&wu, g_wu);
    cudaGetSymbolAddress((void**)&wd, g_wd);
    cudaGetSymbolAddress((void**)&sg, g_sg); cudaGetSymbolAddress((void**)&su, g_su);
    cudaGetSymbolAddress((void**)&sd, g_sd);

    init_kernel<<<1, 32>>>();
    const int CT = 256;
    int n4;
    n4 = NT * HDIM / 4;
    conv_f16_kernel<<<(n4 + CT - 1) / CT, CT>>>(x, x16, n4);
    n4 = NE * IDIM * HDIM / 4;
    conv_f16_kernel<<<(n4 + CT - 1) / CT, CT>>>(w_gate, wg, n4);
    conv_f16_kernel<<<(n4 + CT - 1) / CT, CT>>>(w_up, wu, n4);
    conv_f16_kernel<<<(n4 + CT - 1) / CT, CT>>>(w_down, wd, n4);
    n4 = IDIM * HDIM / 4;
    conv_f16_kernel<<<(n4 + CT - 1) / CT, CT>>>(ws_gate, sg, n4);
    conv_f16_kernel<<<(n4 + CT - 1) / CT, CT>>>(ws_up, su, n4);
    conv_f16_kernel<<<(n4 + CT - 1) / CT, CT>>>(ws_down, sd, n4);

    gate_kernel<<<NT / 8, 256>>>(x, gate_w);
    scan_kernel<<<1, 32>>>();
    scatter_kernel<<<(NROUTED + 255) / 256, 256>>>();

    gateup_mma<<<dim3((IDIM + 127) / 128, MAXTILES + NT / 128, 1), 256, GU_SMEM>>>();
    down_mma<<<dim3(HDIM / 128, MAXTILES + NT / 128, 1), 256, DN_SMEM>>>();
    combine_kernel<<<(NT * (HDIM / 4) + 255) / 256, 256>>>(out);
}

// round 8
// speedup vs baseline: 1.4709x; 1.4709x over previous
#include <cuda_runtime.h>
#include <cuda_fp16.h>
#include <math.h>
#include <stdint.h>

#define HDIM 1024
#define IDIM 2752
#define NE   8
#define NT   4096
#define NROUTED (2*NT)
#define NRP  9216
#define SHB  9216
#define NEP  (NRP + NT)
#define MAXTILES 72

// ---------------- scratch ----------------
__device__ int   g_counts[NE];
__device__ int   g_offp[NE];
__device__ int   g_cursor[NE];
__device__ int   g_tile_e[MAXTILES];
__device__ int   g_tile_m[MAXTILES];
__device__ int   g_topk_idx[NROUTED];
__device__ float g_topk_w[NROUTED];
__device__ int   g_perm[NRP];
__device__ float g_wgt[NRP];
__device__ int   g_entry_of[NROUTED];

__device__ __half g_x16[(size_t)NT * HDIM];
__device__ __half g_wg[(size_t)NE * IDIM * HDIM];
__device__ __half g_wu[(size_t)NE * IDIM * HDIM];
__device__ __half g_wd[(size_t)NE * HDIM * IDIM];
__device__ __half g_sg[(size_t)IDIM * HDIM];
__device__ __half g_su[(size_t)IDIM * HDIM];
__device__ __half g_sd[(size_t)HDIM * IDIM];
__device__ __half g_hm[(size_t)NEP * IDIM];
__device__ float  g_eo[(size_t)NEP * HDIM];

// ---------------- helpers ----------------
__device__ __forceinline__ uint32_t smem_u32(const void* p) {
    uint32_t a;
    asm("{ .reg .u64 t; cvta.to.shared.u64 t, %1; cvt.u32.u64 %0, t; }"
        : "=r"(a) : "l"(p));
    return a;
}
__device__ __forceinline__ void ldsm4(uint32_t* r, uint32_t a) {
    asm volatile("ldmatrix.sync.aligned.m8n8.x4.shared.b16 {%0,%1,%2,%3}, [%4];"
                 : "=r"(r[0]), "=r"(r[1]), "=r"(r[2]), "=r"(r[3]) : "r"(a));
}
__device__ __forceinline__ void mma16816(float* c, const uint32_t* a,
                                         uint32_t b0, uint32_t b1) {
    asm volatile(
        "mma.sync.aligned.m16n8k16.row.col.f32.f16.f16.f32 "
        "{%0,%1,%2,%3}, {%4,%5,%6,%7}, {%8,%9}, {%0,%1,%2,%3};"
        : "+f"(c[0]), "+f"(c[1]), "+f"(c[2]), "+f"(c[3])
        : "r"(a[0]), "r"(a[1]), "r"(a[2]), "r"(a[3]), "r"(b0), "r"(b1));
}
__device__ __forceinline__ void cpasync16(uint32_t dst, const void* src) {
    asm volatile("cp.async.cg.shared.global [%0], [%1], 16;" :: "r"(dst), "l"(src));
}
#define CP_COMMIT() asm volatile("cp.async.commit_group;" ::: "memory")
#define CP_WAIT1()  asm volatile("cp.async.wait_group 1;" ::: "memory")
#define CP_WAIT0()  asm volatile("cp.async.wait_group 0;" ::: "memory")

__device__ __forceinline__ uint32_t pack2h(__half a, __half b) {
    return ((uint32_t)__half_as_ushort(b) << 16) | __half_as_ushort(a);
}

// ---------------- small kernels ----------------
__global__ void init_kernel() {
    int i = threadIdx.x;
    if (i < NE) g_counts[i] = 0;
}

// float -> fp16
__global__ void conv_f16_kernel(const float* __restrict__ src,
                                __half* __restrict__ h, int n4) {
    int i = blockIdx.x * blockDim.x + threadIdx.x;
    if (i >= n4) return;
    float4 v = ((const float4*)src)[i];
    uint2 ph;
    ph.x = pack2h(__float2half_rn(v.x), __float2half_rn(v.y));
    ph.y = pack2h(__float2half_rn(v.z), __float2half_rn(v.w));
    ((uint2*)h)[i] = ph;
}

__global__ void gate_kernel(const float* __restrict__ x,
                            const float* __restrict__ gw) {
    int warp = (blockIdx.x * blockDim.x + threadIdx.x) >> 5;
    int lane = threadIdx.x & 31;
    if (warp >= NT) return;
    const float4* x4 = (const float4*)(x + (size_t)warp * HDIM);
    const float4* gw4 = (const float4*)gw;
    float acc[NE];
#pragma unroll
    for (int e = 0; e < NE; e++) acc[e] = 0.f;
    for (int h4 = lane; h4 < HDIM / 4; h4 += 32) {
        float4 xv = x4[h4];
#pragma unroll
        for (int e = 0; e < NE; e++) {
            float4 g = gw4[e * (HDIM / 4) + h4];
            acc[e] += xv.x * g.x + xv.y * g.y + xv.z * g.z + xv.w * g.w;
        }
    }
#pragma unroll
    for (int e = 0; e < NE; e++)
#pragma unroll
        for (int off = 16; off > 0; off >>= 1)
            acc[e] += __shfl_down_sync(0xffffffffu, acc[e], off);
    if (lane == 0) {
        float mx = acc[0];
#pragma unroll
        for (int e = 1; e < NE; e++) mx = fmaxf(mx, acc[e]);
        float p[NE], s = 0.f;
#pragma unroll
        for (int e = 0; e < NE; e++) { p[e] = expf(acc[e] - mx); s += p[e]; }
        float inv = 1.f / s;
#pragma unroll
        for (int e = 0; e < NE; e++) p[e] *= inv;
        int i1 = 0; float p1 = p[0];
#pragma unroll
        for (int e = 1; e < NE; e++) if (p[e] > p1) { p1 = p[e]; i1 = e; }
        int i2 = -1; float p2 = -1.f;
#pragma unroll
        for (int e = 0; e < NE; e++) {
            if (e == i1) continue;
            if (p[e] > p2) { p2 = p[e]; i2 = e; }
        }
        float rn = 1.f / (p1 + p2 + 1e-20f);
        g_topk_idx[2 * warp + 0] = i1;
        g_topk_idx[2 * warp + 1] = i2;
        g_topk_w[2 * warp + 0] = p1 * rn;
        g_topk_w[2 * warp + 1] = p2 * rn;
        atomicAdd(&g_counts[i1], 1);
        atomicAdd(&g_counts[i2], 1);
    }
}

__global__ void scan_kernel() {
    if (threadIdx.x == 0) {
        int s = 0, t = 0;
        for (int e = 0; e < NE; e++) {
            g_offp[e] = s;
            g_cursor[e] = s;
            int c = g_counts[e];
            int nt = (c + 127) >> 7;
            for (int m = 0; m < nt; m++) { g_tile_e[t] = e; g_tile_m[t] = m << 7; t++; }
            s += (c + 127) & ~127;
        }
        for (; t < MAXTILES; t++) g_tile_e[t] = -1;
    }
}

__global__ void scatter_kernel() {
    int i = blockIdx.x * blockDim.x + threadIdx.x;
    if (i >= NROUTED) return;
    int t = i >> 1;
    int e = g_topk_idx[i];
    int pos = atomicAdd(&g_cursor[e], 1);
    g_perm[pos] = t;
    g_wgt[pos] = g_topk_w[i];
    g_entry_of[i] = pos;
}

// ---------------- gate+up MMA GEMM ----------------
// block 128x128 (x2 outputs), 8 warps (64x32 warp tiles), BK=64, single-pass fp16
// 2-stage double-buffered (issue-before-wait), smem-staged coalesced epilogue
#define GU_PART  16384
#define GU_STAGE (3 * GU_PART)   // A, G, U
#define GU_SMEM  (2 * GU_STAGE)  // 96KB

__global__ __launch_bounds__(256, 1) void gateup_mma() {
    extern __shared__ char sm[];
    uint32_t sb = smem_u32(sm);
    int tid = threadIdx.x, wid = tid >> 5, lane = tid & 31;

    int y = blockIdx.y;
    int e, m0, base;
    bool is_shared;
    if (y >= MAXTILES) {
        is_shared = true; m0 = (y - MAXTILES) << 7; base = SHB;
    } else {
        e = g_tile_e[y];
        if (e < 0) return;
        is_shared = false; m0 = g_tile_m[y]; base = g_offp[e];
    }
    int n0 = blockIdx.x * 128;
    int N = IDIM - n0; if (N > 128) N = 128;

    const __half* WG = is_shared ? g_sg : g_wg + (size_t)e * IDIM * HDIM;
    const __half* WU = is_shared ? g_su : g_wu + (size_t)e * IDIM * HDIM;

    int lrow = tid >> 1, kb0 = (tid & 1) * 4;
    uint32_t swo[4];
#pragma unroll
    for (int j = 0; j < 4; j++)
        swo[j] = lrow * 128 + (((kb0 + j) ^ (lrow & 7)) << 4);
    int tok = is_shared ? (m0 + lrow) : g_perm[base + m0 + lrow];
    const __half* pA = g_x16 + (size_t)tok * HDIM + kb0 * 8;
    int nr = n0 + lrow; if (nr > IDIM - 1) nr = IDIM - 1;
    const __half* pG = WG + (size_t)nr * HDIM + kb0 * 8;
    const __half* pU = WU + (size_t)nr * HDIM + kb0 * 8;

    auto issue = [&](int s) {
        int k0 = s * 64;
        uint32_t bb = sb + (s & 1) * GU_STAGE;
#pragma unroll
        for (int j = 0; j < 4; j++) {
            cpasync16(bb + 0 * GU_PART + swo[j], pA + k0 + j * 8);
            cpasync16(bb + 1 * GU_PART + swo[j], pG + k0 + j * 8);
            cpasync16(bb + 2 * GU_PART + swo[j], pU + k0 + j * 8);
        }
    };

    int warpM = (wid & 1) * 64;
    int warpN = (wid >> 1) * 32;
    int la = lane & 15, kh = lane >> 4, x7 = la & 7;
    uint32_t rowA[4], rowB[2];
#pragma unroll
    for (int mf = 0; mf < 4; mf++) rowA[mf] = (warpM + mf * 16 + la) * 128;
#pragma unroll
    for (int s2 = 0; s2 < 2; s2++) rowB[s2] = (warpN + s2 * 16 + la) * 128;

    float aG[4][4][4], aU[4][4][4];
#pragma unroll
    for (int mf = 0; mf < 4; mf++)
#pragma unroll
        for (int nf = 0; nf < 4; nf++)
#pragma unroll
            for (int q = 0; q < 4; q++) { aG[mf][nf][q] = 0.f; aU[mf][nf][q] = 0.f; }

    issue(0); CP_COMMIT();
    for (int s = 0; s < 16; s++) {
        if (s < 15) { issue(s + 1); CP_COMMIT(); CP_WAIT1(); }
        else CP_WAIT0();
        __syncthreads();
        uint32_t bb = sb + (s & 1) * GU_STAGE;
#pragma unroll
        for (int k16 = 0; k16 < 4; k16++) {
            uint32_t ko = (uint32_t)(((k16 * 2 + kh) ^ x7) << 4);
            uint32_t A[4][4];
#pragma unroll
            for (int mf = 0; mf < 4; mf++)
                ldsm4(A[mf], bb + 0 * GU_PART + rowA[mf] + ko);
            uint32_t G[2][4], U[2][4];
#pragma unroll
            for (int s2 = 0; s2 < 2; s2++) {
                ldsm4(G[s2], bb + 1 * GU_PART + rowB[s2] + ko);
                ldsm4(U[s2], bb + 2 * GU_PART + rowB[s2] + ko);
            }
#pragma unroll
            for (int mf = 0; mf < 4; mf++)
#pragma unroll
                for (int s2 = 0; s2 < 2; s2++)
#pragma unroll
                    for (int j = 0; j < 2; j++) {
                        int nf = s2 * 2 + j;
                        mma16816(aG[mf][nf], A[mf], G[s2][j], G[s2][2 + j]);
                        mma16816(aU[mf][nf], A[mf], U[s2][j], U[s2][2 + j]);
                    }
        }
        __syncthreads();
    }

    // epilogue: hmid = silu(g)*u -> fp16, staged through smem (stride 68 u32)
    uint32_t* st32 = (uint32_t*)sm;
    int qr = lane >> 2, qc = (lane & 3) * 2;
#pragma unroll
    for (int mf = 0; mf < 4; mf++)
#pragma unroll
        for (int nf = 0; nf < 4; nf++) {
            float* cg = aG[mf][nf];
            float* cu = aU[mf][nf];
            int colp = (warpN + nf * 8 + qc) >> 1;
            int r0 = warpM + mf * 16 + qr;
            float g0 = cg[0], g1 = cg[1], g2 = cg[2], g3 = cg[3];
            float v00 = (g0 / (1.f + expf(-g0))) * cu[0];
            float v01 = (g1 / (1.f + expf(-g1))) * cu[1];
            float v10 = (g2 / (1.f + expf(-g2))) * cu[2];
            float v11 = (g3 / (1.f + expf(-g3))) * cu[3];
            st32[r0 * 68 + colp] = pack2h(__float2half_rn(v00), __float2half_rn(v01));
            st32[(r0 + 8) * 68 + colp] = pack2h(__float2half_rn(v10), __float2half_rn(v11));
        }
    __syncthreads();
    {
        int row = tid >> 1, half = tid & 1;
        size_t gbase = (size_t)(base + m0 + row) * IDIM + n0 + half * 64;
        int sbase = row * 68 + half * 32;
#pragma unroll
        for (int c4 = 0; c4 < 8; c4++) {
            if (half * 64 + c4 * 8 < N) {
                uint4 v = *(uint4*)&st32[sbase + c4 * 4];
                *(uint4*)(g_hm + gbase + c4 * 8) = v;
            }
        }
    }
}

// ---------------- down MMA GEMM ----------------
#define DN_PART  16384
#define DN_STAGE (2 * DN_PART)   // A, B
#define DN_SMEM  67584           // max(2*DN_STAGE=64KB, epilogue 128*132*4=66KB)

__global__ __launch_bounds__(256, 1) void down_mma() {
    extern __shared__ char sm[];
    uint32_t sb = smem_u32(sm);
    int tid = threadIdx.x, wid = tid >> 5, lane = tid & 31;

    int y = blockIdx.y;
    int e, m0, base;
    bool is_shared;
    if (y >= MAXTILES) {
        is_shared = true; m0 = (y - MAXTILES) << 7; base = SHB;
    } else {
        e = g_tile_e[y];
        if (e < 0) return;
        is_shared = false; m0 = g_tile_m[y]; base = g_offp[e];
    }
    int n0 = blockIdx.x * 128;

    const __half* WD = is_shared ? g_sd : g_wd + (size_t)e * HDIM * IDIM;

    int lrow = tid >> 1, kb0 = (tid & 1) * 4;
    uint32_t swo[4];
#pragma unroll
    for (int j = 0; j < 4; j++)
        swo[j] = lrow * 128 + (((kb0 + j) ^ (lrow & 7)) << 4);
    const __half* pA = g_hm + (size_t)(base + m0 + lrow) * IDIM + kb0 * 8;
    const __half* pB = WD + (size_t)(n0 + lrow) * IDIM + kb0 * 8;

    auto issue = [&](int s) {
        int k0 = s * 64;
        uint32_t bb = sb + (s & 1) * DN_STAGE;
#pragma unroll
        for (int j = 0; j < 4; j++) {
            cpasync16(bb + 0 * DN_PART + swo[j], pA + k0 + j * 8);
            cpasync16(bb + 1 * DN_PART + swo[j], pB + k0 + j * 8);
        }
    };

    int warpM = (wid & 1) * 64;
    int warpN = (wid >> 1) * 32;
    int la = lane & 15, kh = lane >> 4, x7 = la & 7;
    uint32_t rowA[4], rowB[2];
#pragma unroll
    for (int mf = 0; mf < 4; mf++) rowA[mf] = (warpM + mf * 16 + la) * 128;
#pragma unroll
    for (int s2 = 0; s2 < 2; s2++) rowB[s2] = (warpN + s2 * 16 + la) * 128;

    float acc[4][4][4];
#pragma unroll
    for (int mf = 0; mf < 4; mf++)
#pragma unroll
        for (int nf = 0; nf < 4; nf++)
#pragma unroll
            for (int q = 0; q < 4; q++) acc[mf][nf][q] = 0.f;

    const int S = IDIM / 64;   // 43
    issue(0); CP_COMMIT();
    for (int s = 0; s < S; s++) {
        if (s < S - 1) { issue(s + 1); CP_COMMIT(); CP_WAIT1(); }
        else CP_WAIT0();
        __syncthreads();
        uint32_t bb = sb + (s & 1) * DN_STAGE;
#pragma unroll
        for (int k16 = 0; k16 < 4; k16++) {
            uint32_t ko = (uint32_t)(((k16 * 2 + kh) ^ x7) << 4);
            uint32_t A[4][4];
#pragma unroll
            for (int mf = 0; mf < 4; mf++)
                ldsm4(A[mf], bb + 0 * DN_PART + rowA[mf] + ko);
            uint32_t B[2][4];
#pragma unroll
            for (int s2 = 0; s2 < 2; s2++)
                ldsm4(B[s2], bb + 1 * DN_PART + rowB[s2] + ko);
#pragma unroll
            for (int mf = 0; mf < 4; mf++)
#pragma unroll
                for (int s2 = 0; s2 < 2; s2++)
#pragma unroll
                    for (int j = 0; j < 2; j++) {
                        int nf = s2 * 2 + j;
                        mma16816(acc[mf][nf], A[mf], B[s2][j], B[s2][2 + j]);
                    }
        }
        __syncthreads();
    }

    // epilogue: scale by routing weight, stage through smem (stride 132 floats)
    float* stf = (float*)sm;
    int qr = lane >> 2, qc = (lane & 3) * 2;
#pragma unroll
    for (int mf = 0; mf < 4; mf++) {
        int r0 = warpM + mf * 16 + qr;
        float w0 = is_shared ? 1.f : g_wgt[base + m0 + r0];
        float w1 = is_shared ? 1.f : g_wgt[base + m0 + r0 + 8];
#pragma unroll
        for (int nf = 0; nf < 4; nf++) {
            int col = warpN + nf * 8 + qc;
            float* c = acc[mf][nf];
            *(float2*)&stf[r0 * 132 + col] = make_float2(c[0] * w0, c[1] * w0);
            *(float2*)&stf[(r0 + 8) * 132 + col] = make_float2(c[2] * w1, c[3] * w1);
        }
    }
    __syncthreads();
    {
        int row = tid >> 1, half = tid & 1;
        float* dst = g_eo + (size_t)(base + m0 + row) * HDIM + n0 + half * 64;
        int src = row * 132 + half * 64;
#pragma unroll
        for (int c4 = 0; c4 < 16; c4++)
            *(uint4*)(dst + c4 * 4) = *(uint4*)&stf[src + c4 * 4];
    }
}

// ---------------- combine ----------------
__global__ void combine_kernel(float* __restrict__ out) {
    int idx = blockIdx.x * blockDim.x + threadIdx.x;
    const int HC = HDIM / 4;
    if (idx >= NT * HC) return;
    int t = idx / HC;
    int c = idx - t * HC;
    const float4* eo4 = (const float4*)g_eo;
    int e1 = g_entry_of[2 * t + 0];
    int e2 = g_entry_of[2 * t + 1];
    float4 a = eo4[(size_t)e1 * HC + c];
    float4 b = eo4[(size_t)e2 * HC + c];
    float4 s = eo4[(size_t)(SHB + t) * HC + c];
    float4 r;
    r.x = a.x + b.x + s.x;
    r.y = a.y + b.y + s.y;
    r.z = a.z + b.z + s.z;
    r.w = a.w + b.w + s.w;
    ((float4*)out)[idx] = r;
}

// ---------------- launch ----------------
extern "C" void kernel_launch(void* const* d_in, const int* in_sizes, int n_in,
                              void* d_out, int out_size) {
    const float* x       = (const float*)d_in[0];
    const float* gate_w  = (const float*)d_in[1];
    const float* w_gate  = (const float*)d_in[2];
    const float* w_up    = (const float*)d_in[3];
    const float* w_down  = (const float*)d_in[4];
    const float* ws_gate = (const float*)d_in[5];
    const float* ws_up   = (const float*)d_in[6];
    const float* ws_down = (const float*)d_in[7];
    float* out = (float*)d_out;

    cudaFuncSetAttribute(gateup_mma, cudaFuncAttributeMaxDynamicSharedMemorySize, GU_SMEM);
    cudaFuncSetAttribute(down_mma,   cudaFuncAttributeMaxDynamicSharedMemorySize, DN_SMEM);

    __half *x16, *wg, *wu, *wd, *sg, *su, *sd;
    cudaGetSymbolAddress((void**)&x16, g_x16);
    cudaGetSymbolAddress((void**)&wg, g_wg); cudaGetSymbolAddress((void**)&wu, g_wu);
    cudaGetSymbolAddress((void**)&wd, g_wd);
    cudaGetSymbolAddress((void**)&sg, g_sg); cudaGetSymbolAddress((void**)&su, g_su);
    cudaGetSymbolAddress((void**)&sd, g_sd);

    init_kernel<<<1, 32>>>();
    const int CT = 256;
    int n4;
    n4 = NT * HDIM / 4;
    conv_f16_kernel<<<(n4 + CT - 1) / CT, CT>>>(x, x16, n4);
    n4 = NE * IDIM * HDIM / 4;
    conv_f16_kernel<<<(n4 + CT - 1) / CT, CT>>>(w_gate, wg, n4);
    conv_f16_kernel<<<(n4 + CT - 1) / CT, CT>>>(w_up, wu, n4);
    conv_f16_kernel<<<(n4 + CT - 1) / CT, CT>>>(w_down, wd, n4);
    n4 = IDIM * HDIM / 4;
    conv_f16_kernel<<<(n4 + CT - 1) / CT, CT>>>(ws_gate, sg, n4);
    conv_f16_kernel<<<(n4 + CT - 1) / CT, CT>>>(ws_up, su, n4);
    conv_f16_kernel<<<(n4 + CT - 1) / CT, CT>>>(ws_down, sd, n4);

    gate_kernel<<<NT / 8, 256>>>(x, gate_w);
    scan_kernel<<<1, 32>>>();
    scatter_kernel<<<(NROUTED + 255) / 256, 256>>>();

    gateup_mma<<<dim3((IDIM + 127) / 128, MAXTILES + NT / 128, 1), 256, GU_SMEM>>>();
    down_mma<<<dim3(HDIM / 128, MAXTILES + NT / 128, 1), 256, DN_SMEM>>>();
    combine_kernel<<<(NT * (HDIM / 4) + 255) / 256, 256>>>(out);
}

// round 9
// speedup vs baseline: 1.5092x; 1.0261x over previous
#include <cuda_runtime.h>
#include <cuda_fp16.h>
#include <math.h>
#include <stdint.h>

#define HDIM 1024
#define IDIM 2752
#define NE   8
#define NT   4096
#define NROUTED (2*NT)
#define NRP  9216
#define SHB  9216
#define NEP  (NRP + NT)
#define MAXTILES 72

// ---------------- scratch ----------------
__device__ int   g_counts[NE];
__device__ int   g_offp[NE];
__device__ int   g_cursor[NE];
__device__ int   g_tile_e[MAXTILES];
__device__ int   g_tile_m[MAXTILES];
__device__ int   g_topk_idx[NROUTED];
__device__ float g_topk_w[NROUTED];
__device__ int   g_perm[NRP];
__device__ float g_wgt[NRP];
__device__ int   g_entry_of[NROUTED];

__device__ __half g_x16[(size_t)NT * HDIM];
__device__ __half g_wg[(size_t)NE * IDIM * HDIM];
__device__ __half g_wu[(size_t)NE * IDIM * HDIM];
__device__ __half g_wd[(size_t)NE * HDIM * IDIM];
__device__ __half g_sg[(size_t)IDIM * HDIM];
__device__ __half g_su[(size_t)IDIM * HDIM];
__device__ __half g_sd[(size_t)HDIM * IDIM];
__device__ __half g_hm[(size_t)NEP * IDIM];
__device__ float  g_eo[(size_t)NEP * HDIM];

// ---------------- helpers ----------------
__device__ __forceinline__ uint32_t smem_u32(const void* p) {
    uint32_t a;
    asm("{ .reg .u64 t; cvta.to.shared.u64 t, %1; cvt.u32.u64 %0, t; }"
        : "=r"(a) : "l"(p));
    return a;
}
__device__ __forceinline__ void ldsm4(uint32_t* r, uint32_t a) {
    asm volatile("ldmatrix.sync.aligned.m8n8.x4.shared.b16 {%0,%1,%2,%3}, [%4];"
                 : "=r"(r[0]), "=r"(r[1]), "=r"(r[2]), "=r"(r[3]) : "r"(a));
}
__device__ __forceinline__ void mma16816(float* c, const uint32_t* a,
                                         uint32_t b0, uint32_t b1) {
    asm volatile(
        "mma.sync.aligned.m16n8k16.row.col.f32.f16.f16.f32 "
        "{%0,%1,%2,%3}, {%4,%5,%6,%7}, {%8,%9}, {%0,%1,%2,%3};"
        : "+f"(c[0]), "+f"(c[1]), "+f"(c[2]), "+f"(c[3])
        : "r"(a[0]), "r"(a[1]), "r"(a[2]), "r"(a[3]), "r"(b0), "r"(b1));
}
__device__ __forceinline__ void cpasync16(uint32_t dst, const void* src) {
    asm volatile("cp.async.cg.shared.global [%0], [%1], 16;" :: "r"(dst), "l"(src));
}
#define CP_COMMIT() asm volatile("cp.async.commit_group;" ::: "memory")
#define CP_WAIT1()  asm volatile("cp.async.wait_group 1;" ::: "memory")
#define CP_WAIT0()  asm volatile("cp.async.wait_group 0;" ::: "memory")

__device__ __forceinline__ uint32_t pack2h(__half a, __half b) {
    return ((uint32_t)__half_as_ushort(b) << 16) | __half_as_ushort(a);
}

// ---------------- small kernels ----------------
__global__ void init_kernel() {
    int i = threadIdx.x;
    if (i < NE) g_counts[i] = 0;
}

// float -> fp16
__global__ void conv_f16_kernel(const float* __restrict__ src,
                                __half* __restrict__ h, int n4) {
    int i = blockIdx.x * blockDim.x + threadIdx.x;
    if (i >= n4) return;
    float4 v = ((const float4*)src)[i];
    uint2 ph;
    ph.x = pack2h(__float2half_rn(v.x), __float2half_rn(v.y));
    ph.y = pack2h(__float2half_rn(v.z), __float2half_rn(v.w));
    ((uint2*)h)[i] = ph;
}

__global__ void gate_kernel(const float* __restrict__ x,
                            const float* __restrict__ gw) {
    int warp = (blockIdx.x * blockDim.x + threadIdx.x) >> 5;
    int lane = threadIdx.x & 31;
    if (warp >= NT) return;
    const float4* x4 = (const float4*)(x + (size_t)warp * HDIM);
    const float4* gw4 = (const float4*)gw;
    float acc[NE];
#pragma unroll
    for (int e = 0; e < NE; e++) acc[e] = 0.f;
    for (int h4 = lane; h4 < HDIM / 4; h4 += 32) {
        float4 xv = x4[h4];
#pragma unroll
        for (int e = 0; e < NE; e++) {
            float4 g = gw4[e * (HDIM / 4) + h4];
            acc[e] += xv.x * g.x + xv.y * g.y + xv.z * g.z + xv.w * g.w;
        }
    }
#pragma unroll
    for (int e = 0; e < NE; e++)
#pragma unroll
        for (int off = 16; off > 0; off >>= 1)
            acc[e] += __shfl_down_sync(0xffffffffu, acc[e], off);
    if (lane == 0) {
        float mx = acc[0];
#pragma unroll
        for (int e = 1; e < NE; e++) mx = fmaxf(mx, acc[e]);
        float p[NE], s = 0.f;
#pragma unroll
        for (int e = 0; e < NE; e++) { p[e] = expf(acc[e] - mx); s += p[e]; }
        float inv = 1.f / s;
#pragma unroll
        for (int e = 0; e < NE; e++) p[e] *= inv;
        int i1 = 0; float p1 = p[0];
#pragma unroll
        for (int e = 1; e < NE; e++) if (p[e] > p1) { p1 = p[e]; i1 = e; }
        int i2 = -1; float p2 = -1.f;
#pragma unroll
        for (int e = 0; e < NE; e++) {
            if (e == i1) continue;
            if (p[e] > p2) { p2 = p[e]; i2 = e; }
        }
        float rn = 1.f / (p1 + p2 + 1e-20f);
        g_topk_idx[2 * warp + 0] = i1;
        g_topk_idx[2 * warp + 1] = i2;
        g_topk_w[2 * warp + 0] = p1 * rn;
        g_topk_w[2 * warp + 1] = p2 * rn;
        atomicAdd(&g_counts[i1], 1);
        atomicAdd(&g_counts[i2], 1);
    }
}

__global__ void scan_kernel() {
    if (threadIdx.x == 0) {
        int s = 0, t = 0;
        for (int e = 0; e < NE; e++) {
            g_offp[e] = s;
            g_cursor[e] = s;
            int c = g_counts[e];
            int nt = (c + 127) >> 7;
            for (int m = 0; m < nt; m++) { g_tile_e[t] = e; g_tile_m[t] = m << 7; t++; }
            s += (c + 127) & ~127;
        }
        for (; t < MAXTILES; t++) g_tile_e[t] = -1;
    }
}

__global__ void scatter_kernel() {
    int i = blockIdx.x * blockDim.x + threadIdx.x;
    if (i >= NROUTED) return;
    int t = i >> 1;
    int e = g_topk_idx[i];
    int pos = atomicAdd(&g_cursor[e], 1);
    g_perm[pos] = t;
    g_wgt[pos] = g_topk_w[i];
    g_entry_of[i] = pos;
}

// ---------------- gate+up MMA GEMM ----------------
// block 128x128 (x2 outputs), 8 warps (64x32 warp tiles), BK=64, single-pass fp16
#define GU_PART  16384
#define GU_STAGE (3 * GU_PART)   // A, G, U
#define GU_SMEM  (2 * GU_STAGE)  // 96KB

__global__ __launch_bounds__(256, 1) void gateup_mma() {
    extern __shared__ char sm[];
    uint32_t sb = smem_u32(sm);
    int tid = threadIdx.x, wid = tid >> 5, lane = tid & 31;

    int y = blockIdx.y;
    int e, m0, base;
    bool is_shared;
    if (y >= MAXTILES) {
        is_shared = true; m0 = (y - MAXTILES) << 7; base = SHB;
    } else {
        e = g_tile_e[y];
        if (e < 0) return;
        is_shared = false; m0 = g_tile_m[y]; base = g_offp[e];
    }
    int n0 = blockIdx.x * 128;

    const __half* WG = is_shared ? g_sg : g_wg + (size_t)e * IDIM * HDIM;
    const __half* WU = is_shared ? g_su : g_wu + (size_t)e * IDIM * HDIM;

    int lrow = tid >> 1, kb0 = (tid & 1) * 4;
    uint32_t swo[4];
#pragma unroll
    for (int j = 0; j < 4; j++)
        swo[j] = lrow * 128 + (((kb0 + j) ^ (lrow & 7)) << 4);
    int tok = is_shared ? (m0 + lrow) : g_perm[base + m0 + lrow];
    const __half* pA = g_x16 + (size_t)tok * HDIM + kb0 * 8;
    int nr = n0 + lrow; if (nr > IDIM - 1) nr = IDIM - 1;
    const __half* pG = WG + (size_t)nr * HDIM + kb0 * 8;
    const __half* pU = WU + (size_t)nr * HDIM + kb0 * 8;

    auto issue = [&](int s) {
        int k0 = s * 64;
        uint32_t bb = sb + (s & 1) * GU_STAGE;
#pragma unroll
        for (int j = 0; j < 4; j++) {
            cpasync16(bb + 0 * GU_PART + swo[j], pA + k0 + j * 8);
            cpasync16(bb + 1 * GU_PART + swo[j], pG + k0 + j * 8);
            cpasync16(bb + 2 * GU_PART + swo[j], pU + k0 + j * 8);
        }
    };

    int warpM = (wid & 1) * 64;
    int warpN = (wid >> 1) * 32;
    int la = lane & 15, kh = lane >> 4, x7 = la & 7;
    uint32_t rowA[4], rowB[2];
#pragma unroll
    for (int mf = 0; mf < 4; mf++) rowA[mf] = (warpM + mf * 16 + la) * 128;
#pragma unroll
    for (int s2 = 0; s2 < 2; s2++) rowB[s2] = (warpN + s2 * 16 + la) * 128;

    float aG[4][4][4], aU[4][4][4];
#pragma unroll
    for (int mf = 0; mf < 4; mf++)
#pragma unroll
        for (int nf = 0; nf < 4; nf++)
#pragma unroll
            for (int q = 0; q < 4; q++) { aG[mf][nf][q] = 0.f; aU[mf][nf][q] = 0.f; }

    issue(0); CP_COMMIT();
    for (int s = 0; s < 16; s++) {
        if (s < 15) { issue(s + 1); CP_COMMIT(); CP_WAIT1(); }
        else CP_WAIT0();
        __syncthreads();
        uint32_t bb = sb + (s & 1) * GU_STAGE;
#pragma unroll
        for (int k16 = 0; k16 < 4; k16++) {
            uint32_t ko = (uint32_t)(((k16 * 2 + kh) ^ x7) << 4);
            uint32_t A[4][4];
#pragma unroll
            for (int mf = 0; mf < 4; mf++)
                ldsm4(A[mf], bb + 0 * GU_PART + rowA[mf] + ko);
            uint32_t G[2][4], U[2][4];
#pragma unroll
            for (int s2 = 0; s2 < 2; s2++) {
                ldsm4(G[s2], bb + 1 * GU_PART + rowB[s2] + ko);
                ldsm4(U[s2], bb + 2 * GU_PART + rowB[s2] + ko);
            }
#pragma unroll
            for (int mf = 0; mf < 4; mf++)
#pragma unroll
                for (int s2 = 0; s2 < 2; s2++)
#pragma unroll
                    for (int j = 0; j < 2; j++) {
                        int nf = s2 * 2 + j;
                        mma16816(aG[mf][nf], A[mf], G[s2][j], G[s2][2 + j]);
                        mma16816(aU[mf][nf], A[mf], U[s2][j], U[s2][2 + j]);
                    }
        }
        __syncthreads();
    }

    // epilogue: hmid = silu(g)*u -> fp16
    int qr = lane >> 2, qc = (lane & 3) * 2;
#pragma unroll
    for (int mf = 0; mf < 4; mf++)
#pragma unroll
        for (int nf = 0; nf < 4; nf++) {
            int col = n0 + warpN + nf * 8 + qc;
            if (col >= IDIM) continue;
            float* cg = aG[mf][nf];
            float* cu = aU[mf][nf];
            int r0 = m0 + warpM + mf * 16 + qr;
            float g0 = cg[0], g1 = cg[1], g2 = cg[2], g3 = cg[3];
            float v00 = (g0 / (1.f + expf(-g0))) * cu[0];
            float v01 = (g1 / (1.f + expf(-g1))) * cu[1];
            float v10 = (g2 / (1.f + expf(-g2))) * cu[2];
            float v11 = (g3 / (1.f + expf(-g3))) * cu[3];
            uint32_t p0 = pack2h(__float2half_rn(v00), __float2half_rn(v01));
            uint32_t p1 = pack2h(__float2half_rn(v10), __float2half_rn(v11));
            size_t o0 = (size_t)(base + r0) * IDIM + col;
            size_t o1 = o0 + (size_t)8 * IDIM;
            *(uint32_t*)(g_hm + o0) = p0;
            *(uint32_t*)(g_hm + o1) = p1;
        }
}

// ---------------- down MMA GEMM ----------------
// 2 blocks/SM: barrier + tail hiding via co-residency
#define DN_PART  16384
#define DN_STAGE (2 * DN_PART)   // A, B
#define DN_SMEM  (2 * DN_STAGE)  // 64KB

__global__ __launch_bounds__(256, 2) void down_mma() {
    extern __shared__ char sm[];
    uint32_t sb = smem_u32(sm);
    int tid = threadIdx.x, wid = tid >> 5, lane = tid & 31;

    int y = blockIdx.y;
    int e, m0, base;
    bool is_shared;
    if (y >= MAXTILES) {
        is_shared = true; m0 = (y - MAXTILES) << 7; base = SHB;
    } else {
        e = g_tile_e[y];
        if (e < 0) return;
        is_shared = false; m0 = g_tile_m[y]; base = g_offp[e];
    }
    int n0 = blockIdx.x * 128;

    const __half* WD = is_shared ? g_sd : g_wd + (size_t)e * HDIM * IDIM;

    int lrow = tid >> 1, kb0 = (tid & 1) * 4;
    uint32_t swo[4];
#pragma unroll
    for (int j = 0; j < 4; j++)
        swo[j] = lrow * 128 + (((kb0 + j) ^ (lrow & 7)) << 4);
    const __half* pA = g_hm + (size_t)(base + m0 + lrow) * IDIM + kb0 * 8;
    const __half* pB = WD + (size_t)(n0 + lrow) * IDIM + kb0 * 8;

    auto issue = [&](int s) {
        int k0 = s * 64;
        uint32_t bb = sb + (s & 1) * DN_STAGE;
#pragma unroll
        for (int j = 0; j < 4; j++) {
            cpasync16(bb + 0 * DN_PART + swo[j], pA + k0 + j * 8);
            cpasync16(bb + 1 * DN_PART + swo[j], pB + k0 + j * 8);
        }
    };

    int warpM = (wid & 1) * 64;
    int warpN = (wid >> 1) * 32;
    int la = lane & 15, kh = lane >> 4, x7 = la & 7;
    uint32_t rowA[4], rowB[2];
#pragma unroll
    for (int mf = 0; mf < 4; mf++) rowA[mf] = (warpM + mf * 16 + la) * 128;
#pragma unroll
    for (int s2 = 0; s2 < 2; s2++) rowB[s2] = (warpN + s2 * 16 + la) * 128;

    float acc[4][4][4];
#pragma unroll
    for (int mf = 0; mf < 4; mf++)
#pragma unroll
        for (int nf = 0; nf < 4; nf++)
#pragma unroll
            for (int q = 0; q < 4; q++) acc[mf][nf][q] = 0.f;

    const int S = IDIM / 64;   // 43
    issue(0); CP_COMMIT();
    for (int s = 0; s < S; s++) {
        if (s < S - 1) { issue(s + 1); CP_COMMIT(); CP_WAIT1(); }
        else CP_WAIT0();
        __syncthreads();
        uint32_t bb = sb + (s & 1) * DN_STAGE;
#pragma unroll
        for (int k16 = 0; k16 < 4; k16++) {
            uint32_t ko = (uint32_t)(((k16 * 2 + kh) ^ x7) << 4);
            uint32_t A[4][4];
#pragma unroll
            for (int mf = 0; mf < 4; mf++)
                ldsm4(A[mf], bb + 0 * DN_PART + rowA[mf] + ko);
            uint32_t B[2][4];
#pragma unroll
            for (int s2 = 0; s2 < 2; s2++)
                ldsm4(B[s2], bb + 1 * DN_PART + rowB[s2] + ko);
#pragma unroll
            for (int mf = 0; mf < 4; mf++)
#pragma unroll
                for (int s2 = 0; s2 < 2; s2++)
#pragma unroll
                    for (int j = 0; j < 2; j++) {
                        int nf = s2 * 2 + j;
                        mma16816(acc[mf][nf], A[mf], B[s2][j], B[s2][2 + j]);
                    }
        }
        __syncthreads();
    }

    int qr = lane >> 2, qc = (lane & 3) * 2;
#pragma unroll
    for (int mf = 0; mf < 4; mf++) {
        int r0 = m0 + warpM + mf * 16 + qr;
        float w0 = is_shared ? 1.f : g_wgt[base + r0];
        float w1 = is_shared ? 1.f : g_wgt[base + r0 + 8];
#pragma unroll
        for (int nf = 0; nf < 4; nf++) {
            int col = n0 + warpN + nf * 8 + qc;
            float* c = acc[mf][nf];
            size_t o0 = (size_t)(base + r0) * HDIM + col;
            size_t o1 = o0 + (size_t)8 * HDIM;
            float2 v0 = make_float2(c[0] * w0, c[1] * w0);
            float2 v1 = make_float2(c[2] * w1, c[3] * w1);
            *(float2*)(g_eo + o0) = v0;
            *(float2*)(g_eo + o1) = v1;
        }
    }
}

// ---------------- combine ----------------
__global__ void combine_kernel(float* __restrict__ out) {
    int idx = blockIdx.x * blockDim.x + threadIdx.x;
    const int HC = HDIM / 4;
    if (idx >= NT * HC) return;
    int t = idx / HC;
    int c = idx - t * HC;
    const float4* eo4 = (const float4*)g_eo;
    int e1 = g_entry_of[2 * t + 0];
    int e2 = g_entry_of[2 * t + 1];
    float4 a = eo4[(size_t)e1 * HC + c];
    float4 b = eo4[(size_t)e2 * HC + c];
    float4 s = eo4[(size_t)(SHB + t) * HC + c];
    float4 r;
    r.x = a.x + b.x + s.x;
    r.y = a.y + b.y + s.y;
    r.z = a.z + b.z + s.z;
    r.w = a.w + b.w + s.w;
    ((float4*)out)[idx] = r;
}

// ---------------- launch ----------------
extern "C" void kernel_launch(void* const* d_in, const int* in_sizes, int n_in,
                              void* d_out, int out_size) {
    const float* x       = (const float*)d_in[0];
    const float* gate_w  = (const float*)d_in[1];
    const float* w_gate  = (const float*)d_in[2];
    const float* w_up    = (const float*)d_in[3];
    const float* w_down  = (const float*)d_in[4];
    const float* ws_gate = (const float*)d_in[5];
    const float* ws_up   = (const float*)d_in[6];
    const float* ws_down = (const float*)d_in[7];
    float* out = (float*)d_out;

    cudaFuncSetAttribute(gateup_mma, cudaFuncAttributeMaxDynamicSharedMemorySize, GU_SMEM);
    cudaFuncSetAttribute(down_mma,   cudaFuncAttributeMaxDynamicSharedMemorySize, DN_SMEM);

    __half *x16, *wg, *wu, *wd, *sg, *su, *sd;
    cudaGetSymbolAddress((void**)&x16, g_x16);
    cudaGetSymbolAddress((void**)&wg, g_wg); cudaGetSymbolAddress((void**)&wu, g_wu);
    cudaGetSymbolAddress((void**)&wd, g_wd);
    cudaGetSymbolAddress((void**)&sg, g_sg); cudaGetSymbolAddress((void**)&su, g_su);
    cudaGetSymbolAddress((void**)&sd, g_sd);

    init_kernel<<<1, 32>>>();
    const int CT = 256;
    int n4;
    n4 = NT * HDIM / 4;
    conv_f16_kernel<<<(n4 + CT - 1) / CT, CT>>>(x, x16, n4);
    n4 = NE * IDIM * HDIM / 4;
    conv_f16_kernel<<<(n4 + CT - 1) / CT, CT>>>(w_gate, wg, n4);
    conv_f16_kernel<<<(n4 + CT - 1) / CT, CT>>>(w_up, wu, n4);
    conv_f16_kernel<<<(n4 + CT - 1) / CT, CT>>>(w_down, wd, n4);
    n4 = IDIM * HDIM / 4;
    conv_f16_kernel<<<(n4 + CT - 1) / CT, CT>>>(ws_gate, sg, n4);
    conv_f16_kernel<<<(n4 + CT - 1) / CT, CT>>>(ws_up, su, n4);
    conv_f16_kernel<<<(n4 + CT - 1) / CT, CT>>>(ws_down, sd, n4);

    gate_kernel<<<NT / 8, 256>>>(x, gate_w);
    scan_kernel<<<1, 32>>>();
    scatter_kernel<<<(NROUTED + 255) / 256, 256>>>();

    gateup_mma<<<dim3((IDIM + 127) / 128, MAXTILES + NT / 128, 1), 256, GU_SMEM>>>();
    down_mma<<<dim3(HDIM / 128, MAXTILES + NT / 128, 1), 256, DN_SMEM>>>();
    combine_kernel<<<(NT * (HDIM / 4) + 255) / 256, 256>>>(out);
}

// round 10
// speedup vs baseline: 1.5416x; 1.0214x over previous
#include <cuda_runtime.h>
#include <cuda_fp16.h>
#include <math.h>
#include <stdint.h>

#define HDIM 1024
#define IDIM 2752
#define NE   8
#define NT   4096
#define NROUTED (2*NT)
#define NRP  9216
#define SHB  9216
#define NEP  (NRP + NT)
#define MAXTILES 72

// ---------------- scratch ----------------
__device__ int   g_counts[NE];
__device__ int   g_offp[NE];
__device__ int   g_cursor[NE];
__device__ int   g_tile_e[MAXTILES];
__device__ int   g_tile_m[MAXTILES];
__device__ int   g_topk_idx[NROUTED];
__device__ float g_topk_w[NROUTED];
__device__ int   g_perm[NRP];
__device__ float g_wgt[NRP];
__device__ int   g_entry_of[NROUTED];

__device__ __half g_x16[(size_t)NT * HDIM];
__device__ __half g_wg[(size_t)NE * IDIM * HDIM];
__device__ __half g_wu[(size_t)NE * IDIM * HDIM];
__device__ __half g_wd[(size_t)NE * HDIM * IDIM];
__device__ __half g_sg[(size_t)IDIM * HDIM];
__device__ __half g_su[(size_t)IDIM * HDIM];
__device__ __half g_sd[(size_t)HDIM * IDIM];
__device__ __half g_hm[(size_t)NEP * IDIM];
__device__ float  g_eo[(size_t)NEP * HDIM];

// ---------------- helpers ----------------
__device__ __forceinline__ uint32_t smem_u32(const void* p) {
    uint32_t a;
    asm("{ .reg .u64 t; cvta.to.shared.u64 t, %1; cvt.u32.u64 %0, t; }"
        : "=r"(a) : "l"(p));
    return a;
}
__device__ __forceinline__ void ldsm4(uint32_t* r, uint32_t a) {
    asm volatile("ldmatrix.sync.aligned.m8n8.x4.shared.b16 {%0,%1,%2,%3}, [%4];"
                 : "=r"(r[0]), "=r"(r[1]), "=r"(r[2]), "=r"(r[3]) : "r"(a));
}
__device__ __forceinline__ void mma16816(float* c, const uint32_t* a,
                                         uint32_t b0, uint32_t b1) {
    asm volatile(
        "mma.sync.aligned.m16n8k16.row.col.f32.f16.f16.f32 "
        "{%0,%1,%2,%3}, {%4,%5,%6,%7}, {%8,%9}, {%0,%1,%2,%3};"
        : "+f"(c[0]), "+f"(c[1]), "+f"(c[2]), "+f"(c[3])
        : "r"(a[0]), "r"(a[1]), "r"(a[2]), "r"(a[3]), "r"(b0), "r"(b1));
}
__device__ __forceinline__ void cpasync16(uint32_t dst, const void* src) {
    asm volatile("cp.async.cg.shared.global [%0], [%1], 16;" :: "r"(dst), "l"(src));
}
#define CP_COMMIT() asm volatile("cp.async.commit_group;" ::: "memory")
#define CP_WAIT1()  asm volatile("cp.async.wait_group 1;" ::: "memory")
#define CP_WAIT0()  asm volatile("cp.async.wait_group 0;" ::: "memory")

__device__ __forceinline__ uint32_t pack2h(__half a, __half b) {
    return ((uint32_t)__half_as_ushort(b) << 16) | __half_as_ushort(a);
}

// ---------------- small kernels ----------------
__global__ void init_kernel() {
    int i = threadIdx.x;
    if (i < NE) g_counts[i] = 0;
}

// one-shot conversion of all 7 tensors; each thread converts 8 floats
struct ConvArgs {
    const float* src[7];
    __half*      dst[7];
    int          cum[8];   // cumulative sizes in 8-float units
};

__global__ void conv_all_kernel(ConvArgs args) {
    int idx = blockIdx.x * blockDim.x + threadIdx.x;
    if (idx >= args.cum[7]) return;
    int s = 0;
#pragma unroll
    for (int k = 1; k < 7; k++)
        if (idx >= args.cum[k]) s = k;
    size_t off = (size_t)(idx - args.cum[s]) * 8;
    const float4* p = (const float4*)(args.src[s] + off);
    float4 a = p[0], b = p[1];
    uint4 o;
    o.x = pack2h(__float2half_rn(a.x), __float2half_rn(a.y));
    o.y = pack2h(__float2half_rn(a.z), __float2half_rn(a.w));
    o.z = pack2h(__float2half_rn(b.x), __float2half_rn(b.y));
    o.w = pack2h(__float2half_rn(b.z), __float2half_rn(b.w));
    *(uint4*)(args.dst[s] + off) = o;
}

__global__ void gate_kernel(const float* __restrict__ x,
                            const float* __restrict__ gw) {
    int warp = (blockIdx.x * blockDim.x + threadIdx.x) >> 5;
    int lane = threadIdx.x & 31;
    if (warp >= NT) return;
    const float4* x4 = (const float4*)(x + (size_t)warp * HDIM);
    const float4* gw4 = (const float4*)gw;
    float acc[NE];
#pragma unroll
    for (int e = 0; e < NE; e++) acc[e] = 0.f;
    for (int h4 = lane; h4 < HDIM / 4; h4 += 32) {
        float4 xv = x4[h4];
#pragma unroll
        for (int e = 0; e < NE; e++) {
            float4 g = gw4[e * (HDIM / 4) + h4];
            acc[e] += xv.x * g.x + xv.y * g.y + xv.z * g.z + xv.w * g.w;
        }
    }
#pragma unroll
    for (int e = 0; e < NE; e++)
#pragma unroll
        for (int off = 16; off > 0; off >>= 1)
            acc[e] += __shfl_down_sync(0xffffffffu, acc[e], off);
    if (lane == 0) {
        float mx = acc[0];
#pragma unroll
        for (int e = 1; e < NE; e++) mx = fmaxf(mx, acc[e]);
        float p[NE], s = 0.f;
#pragma unroll
        for (int e = 0; e < NE; e++) { p[e] = expf(acc[e] - mx); s += p[e]; }
        float inv = 1.f / s;
#pragma unroll
        for (int e = 0; e < NE; e++) p[e] *= inv;
        int i1 = 0; float p1 = p[0];
#pragma unroll
        for (int e = 1; e < NE; e++) if (p[e] > p1) { p1 = p[e]; i1 = e; }
        int i2 = -1; float p2 = -1.f;
#pragma unroll
        for (int e = 0; e < NE; e++) {
            if (e == i1) continue;
            if (p[e] > p2) { p2 = p[e]; i2 = e; }
        }
        float rn = 1.f / (p1 + p2 + 1e-20f);
        g_topk_idx[2 * warp + 0] = i1;
        g_topk_idx[2 * warp + 1] = i2;
        g_topk_w[2 * warp + 0] = p1 * rn;
        g_topk_w[2 * warp + 1] = p2 * rn;
        atomicAdd(&g_counts[i1], 1);
        atomicAdd(&g_counts[i2], 1);
    }
}

__global__ void scan_kernel() {
    if (threadIdx.x == 0) {
        int s = 0, t = 0;
        for (int e = 0; e < NE; e++) {
            g_offp[e] = s;
            g_cursor[e] = s;
            int c = g_counts[e];
            int nt = (c + 127) >> 7;
            for (int m = 0; m < nt; m++) { g_tile_e[t] = e; g_tile_m[t] = m << 7; t++; }
            s += (c + 127) & ~127;
        }
        for (; t < MAXTILES; t++) g_tile_e[t] = -1;
    }
}

__global__ void scatter_kernel() {
    int i = blockIdx.x * blockDim.x + threadIdx.x;
    if (i >= NROUTED) return;
    int t = i >> 1;
    int e = g_topk_idx[i];
    int pos = atomicAdd(&g_cursor[e], 1);
    g_perm[pos] = t;
    g_wgt[pos] = g_topk_w[i];
    g_entry_of[i] = pos;
}

// ---------------- gate+up MMA GEMM ----------------
// block 128x128 (x2 outputs), 8 warps (64x32 warp tiles), BK=64, single-pass fp16
#define GU_PART  16384
#define GU_STAGE (3 * GU_PART)   // A, G, U
#define GU_SMEM  (2 * GU_STAGE)  // 96KB

__global__ __launch_bounds__(256, 1) void gateup_mma() {
    extern __shared__ char sm[];
    uint32_t sb = smem_u32(sm);
    int tid = threadIdx.x, wid = tid >> 5, lane = tid & 31;

    int y = blockIdx.y;
    int e, m0, base;
    bool is_shared;
    if (y >= MAXTILES) {
        is_shared = true; m0 = (y - MAXTILES) << 7; base = SHB;
    } else {
        e = g_tile_e[y];
        if (e < 0) return;
        is_shared = false; m0 = g_tile_m[y]; base = g_offp[e];
    }
    int n0 = blockIdx.x * 128;

    const __half* WG = is_shared ? g_sg : g_wg + (size_t)e * IDIM * HDIM;
    const __half* WU = is_shared ? g_su : g_wu + (size_t)e * IDIM * HDIM;

    int lrow = tid >> 1, kb0 = (tid & 1) * 4;
    uint32_t swo[4];
#pragma unroll
    for (int j = 0; j < 4; j++)
        swo[j] = lrow * 128 + (((kb0 + j) ^ (lrow & 7)) << 4);
    int tok = is_shared ? (m0 + lrow) : g_perm[base + m0 + lrow];
    const __half* pA = g_x16 + (size_t)tok * HDIM + kb0 * 8;
    int nr = n0 + lrow; if (nr > IDIM - 1) nr = IDIM - 1;
    const __half* pG = WG + (size_t)nr * HDIM + kb0 * 8;
    const __half* pU = WU + (size_t)nr * HDIM + kb0 * 8;

    auto issue = [&](int s) {
        int k0 = s * 64;
        uint32_t bb = sb + (s & 1) * GU_STAGE;
#pragma unroll
        for (int j = 0; j < 4; j++) {
            cpasync16(bb + 0 * GU_PART + swo[j], pA + k0 + j * 8);
            cpasync16(bb + 1 * GU_PART + swo[j], pG + k0 + j * 8);
            cpasync16(bb + 2 * GU_PART + swo[j], pU + k0 + j * 8);
        }
    };

    int warpM = (wid & 1) * 64;
    int warpN = (wid >> 1) * 32;
    int la = lane & 15, kh = lane >> 4, x7 = la & 7;
    uint32_t rowA[4], rowB[2];
#pragma unroll
    for (int mf = 0; mf < 4; mf++) rowA[mf] = (warpM + mf * 16 + la) * 128;
#pragma unroll
    for (int s2 = 0; s2 < 2; s2++) rowB[s2] = (warpN + s2 * 16 + la) * 128;

    float aG[4][4][4], aU[4][4][4];
#pragma unroll
    for (int mf = 0; mf < 4; mf++)
#pragma unroll
        for (int nf = 0; nf < 4; nf++)
#pragma unroll
            for (int q = 0; q < 4; q++) { aG[mf][nf][q] = 0.f; aU[mf][nf][q] = 0.f; }

    issue(0); CP_COMMIT();
    for (int s = 0; s < 16; s++) {
        if (s < 15) { issue(s + 1); CP_COMMIT(); CP_WAIT1(); }
        else CP_WAIT0();
        __syncthreads();
        uint32_t bb = sb + (s & 1) * GU_STAGE;
#pragma unroll
        for (int k16 = 0; k16 < 4; k16++) {
            uint32_t ko = (uint32_t)(((k16 * 2 + kh) ^ x7) << 4);
            uint32_t A[4][4];
#pragma unroll
            for (int mf = 0; mf < 4; mf++)
                ldsm4(A[mf], bb + 0 * GU_PART + rowA[mf] + ko);
            uint32_t G[2][4], U[2][4];
#pragma unroll
            for (int s2 = 0; s2 < 2; s2++) {
                ldsm4(G[s2], bb + 1 * GU_PART + rowB[s2] + ko);
                ldsm4(U[s2], bb + 2 * GU_PART + rowB[s2] + ko);
            }
#pragma unroll
            for (int mf = 0; mf < 4; mf++)
#pragma unroll
                for (int s2 = 0; s2 < 2; s2++)
#pragma unroll
                    for (int j = 0; j < 2; j++) {
                        int nf = s2 * 2 + j;
                        mma16816(aG[mf][nf], A[mf], G[s2][j], G[s2][2 + j]);
                        mma16816(aU[mf][nf], A[mf], U[s2][j], U[s2][2 + j]);
                    }
        }
        __syncthreads();
    }

    // epilogue: hmid = silu(g)*u -> fp16
    int qr = lane >> 2, qc = (lane & 3) * 2;
#pragma unroll
    for (int mf = 0; mf < 4; mf++)
#pragma unroll
        for (int nf = 0; nf < 4; nf++) {
            int col = n0 + warpN + nf * 8 + qc;
            if (col >= IDIM) continue;
            float* cg = aG[mf][nf];
            float* cu = aU[mf][nf];
            int r0 = m0 + warpM + mf * 16 + qr;
            float g0 = cg[0], g1 = cg[1], g2 = cg[2], g3 = cg[3];
            float v00 = (g0 / (1.f + expf(-g0))) * cu[0];
            float v01 = (g1 / (1.f + expf(-g1))) * cu[1];
            float v10 = (g2 / (1.f + expf(-g2))) * cu[2];
            float v11 = (g3 / (1.f + expf(-g3))) * cu[3];
            uint32_t p0 = pack2h(__float2half_rn(v00), __float2half_rn(v01));
            uint32_t p1 = pack2h(__float2half_rn(v10), __float2half_rn(v11));
            size_t o0 = (size_t)(base + r0) * IDIM + col;
            size_t o1 = o0 + (size_t)8 * IDIM;
            *(uint32_t*)(g_hm + o0) = p0;
            *(uint32_t*)(g_hm + o1) = p1;
        }
}

// ---------------- down MMA GEMM ----------------
// 2 blocks/SM: barrier + tail hiding via co-residency
#define DN_PART  16384
#define DN_STAGE (2 * DN_PART)   // A, B
#define DN_SMEM  (2 * DN_STAGE)  // 64KB

__global__ __launch_bounds__(256, 2) void down_mma() {
    extern __shared__ char sm[];
    uint32_t sb = smem_u32(sm);
    int tid = threadIdx.x, wid = tid >> 5, lane = tid & 31;

    int y = blockIdx.y;
    int e, m0, base;
    bool is_shared;
    if (y >= MAXTILES) {
        is_shared = true; m0 = (y - MAXTILES) << 7; base = SHB;
    } else {
        e = g_tile_e[y];
        if (e < 0) return;
        is_shared = false; m0 = g_tile_m[y]; base = g_offp[e];
    }
    int n0 = blockIdx.x * 128;

    const __half* WD = is_shared ? g_sd : g_wd + (size_t)e * HDIM * IDIM;

    int lrow = tid >> 1, kb0 = (tid & 1) * 4;
    uint32_t swo[4];
#pragma unroll
    for (int j = 0; j < 4; j++)
        swo[j] = lrow * 128 + (((kb0 + j) ^ (lrow & 7)) << 4);
    const __half* pA = g_hm + (size_t)(base + m0 + lrow) * IDIM + kb0 * 8;
    const __half* pB = WD + (size_t)(n0 + lrow) * IDIM + kb0 * 8;

    auto issue = [&](int s) {
        int k0 = s * 64;
        uint32_t bb = sb + (s & 1) * DN_STAGE;
#pragma unroll
        for (int j = 0; j < 4; j++) {
            cpasync16(bb + 0 * DN_PART + swo[j], pA + k0 + j * 8);
            cpasync16(bb + 1 * DN_PART + swo[j], pB + k0 + j * 8);
        }
    };

    int warpM = (wid & 1) * 64;
    int warpN = (wid >> 1) * 32;
    int la = lane & 15, kh = lane >> 4, x7 = la & 7;
    uint32_t rowA[4], rowB[2];
#pragma unroll
    for (int mf = 0; mf < 4; mf++) rowA[mf] = (warpM + mf * 16 + la) * 128;
#pragma unroll
    for (int s2 = 0; s2 < 2; s2++) rowB[s2] = (warpN + s2 * 16 + la) * 128;

    float acc[4][4][4];
#pragma unroll
    for (int mf = 0; mf < 4; mf++)
#pragma unroll
        for (int nf = 0; nf < 4; nf++)
#pragma unroll
            for (int q = 0; q < 4; q++) acc[mf][nf][q] = 0.f;

    const int S = IDIM / 64;   // 43
    issue(0); CP_COMMIT();
    for (int s = 0; s < S; s++) {
        if (s < S - 1) { issue(s + 1); CP_COMMIT(); CP_WAIT1(); }
        else CP_WAIT0();
        __syncthreads();
        uint32_t bb = sb + (s & 1) * DN_STAGE;
#pragma unroll
        for (int k16 = 0; k16 < 4; k16++) {
            uint32_t ko = (uint32_t)(((k16 * 2 + kh) ^ x7) << 4);
            uint32_t A[4][4];
#pragma unroll
            for (int mf = 0; mf < 4; mf++)
                ldsm4(A[mf], bb + 0 * DN_PART + rowA[mf] + ko);
            uint32_t B[2][4];
#pragma unroll
            for (int s2 = 0; s2 < 2; s2++)
                ldsm4(B[s2], bb + 1 * DN_PART + rowB[s2] + ko);
#pragma unroll
            for (int mf = 0; mf < 4; mf++)
#pragma unroll
                for (int s2 = 0; s2 < 2; s2++)
#pragma unroll
                    for (int j = 0; j < 2; j++) {
                        int nf = s2 * 2 + j;
                        mma16816(acc[mf][nf], A[mf], B[s2][j], B[s2][2 + j]);
                    }
        }
        __syncthreads();
    }

    int qr = lane >> 2, qc = (lane & 3) * 2;
#pragma unroll
    for (int mf = 0; mf < 4; mf++) {
        int r0 = m0 + warpM + mf * 16 + qr;
        float w0 = is_shared ? 1.f : g_wgt[base + r0];
        float w1 = is_shared ? 1.f : g_wgt[base + r0 + 8];
#pragma unroll
        for (int nf = 0; nf < 4; nf++) {
            int col = n0 + warpN + nf * 8 + qc;
            float* c = acc[mf][nf];
            size_t o0 = (size_t)(base + r0) * HDIM + col;
            size_t o1 = o0 + (size_t)8 * HDIM;
            float2 v0 = make_float2(c[0] * w0, c[1] * w0);
            float2 v1 = make_float2(c[2] * w1, c[3] * w1);
            *(float2*)(g_eo + o0) = v0;
            *(float2*)(g_eo + o1) = v1;
        }
    }
}

// ---------------- combine ----------------
__global__ void combine_kernel(float* __restrict__ out) {
    int idx = blockIdx.x * blockDim.x + threadIdx.x;
    const int HC = HDIM / 4;
    if (idx >= NT * HC) return;
    int t = idx / HC;
    int c = idx - t * HC;
    const float4* eo4 = (const float4*)g_eo;
    int e1 = g_entry_of[2 * t + 0];
    int e2 = g_entry_of[2 * t + 1];
    float4 a = eo4[(size_t)e1 * HC + c];
    float4 b = eo4[(size_t)e2 * HC + c];
    float4 s = eo4[(size_t)(SHB + t) * HC + c];
    float4 r;
    r.x = a.x + b.x + s.x;
    r.y = a.y + b.y + s.y;
    r.z = a.z + b.z + s.z;
    r.w = a.w + b.w + s.w;
    ((float4*)out)[idx] = r;
}

// ---------------- launch ----------------
extern "C" void kernel_launch(void* const* d_in, const int* in_sizes, int n_in,
                              void* d_out, int out_size) {
    const float* x       = (const float*)d_in[0];
    const float* gate_w  = (const float*)d_in[1];
    const float* w_gate  = (const float*)d_in[2];
    const float* w_up    = (const float*)d_in[3];
    const float* w_down  = (const float*)d_in[4];
    const float* ws_gate = (const float*)d_in[5];
    const float* ws_up   = (const float*)d_in[6];
    const float* ws_down = (const float*)d_in[7];
    float* out = (float*)d_out;

    cudaFuncSetAttribute(gateup_mma, cudaFuncAttributeMaxDynamicSharedMemorySize, GU_SMEM);
    cudaFuncSetAttribute(down_mma,   cudaFuncAttributeMaxDynamicSharedMemorySize, DN_SMEM);

    __half *x16, *wg, *wu, *wd, *sg, *su, *sd;
    cudaGetSymbolAddress((void**)&x16, g_x16);
    cudaGetSymbolAddress((void**)&wg, g_wg); cudaGetSymbolAddress((void**)&wu, g_wu);
    cudaGetSymbolAddress((void**)&wd, g_wd);
    cudaGetSymbolAddress((void**)&sg, g_sg); cudaGetSymbolAddress((void**)&su, g_su);
    cudaGetSymbolAddress((void**)&sd, g_sd);

    // segment table (units of 8 floats)
    ConvArgs ca;
    ca.src[0] = x;       ca.dst[0] = x16;
    ca.src[1] = w_gate;  ca.dst[1] = wg;
    ca.src[2] = w_up;    ca.dst[2] = wu;
    ca.src[3] = w_down;  ca.dst[3] = wd;
    ca.src[4] = ws_gate; ca.dst[4] = sg;
    ca.src[5] = ws_up;   ca.dst[5] = su;
    ca.src[6] = ws_down; ca.dst[6] = sd;
    int sz8[7] = {
        NT * HDIM / 8,
        NE * IDIM * HDIM / 8, NE * IDIM * HDIM / 8, NE * IDIM * HDIM / 8,
        IDIM * HDIM / 8, IDIM * HDIM / 8, IDIM * HDIM / 8
    };
    ca.cum[0] = 0;
    for (int i = 0; i < 7; i++) ca.cum[i + 1] = ca.cum[i] + sz8[i];
    int total = ca.cum[7];

    init_kernel<<<1, 32>>>();
    conv_all_kernel<<<(total + 255) / 256, 256>>>(ca);
    gate_kernel<<<NT / 8, 256>>>(x, gate_w);
    scan_kernel<<<1, 32>>>();
    scatter_kernel<<<(NROUTED + 255) / 256, 256>>>();

    gateup_mma<<<dim3((IDIM + 127) / 128, MAXTILES + NT / 128, 1), 256, GU_SMEM>>>();
    down_mma<<<dim3(HDIM / 128, MAXTILES + NT / 128, 1), 256, DN_SMEM>>>();
    combine_kernel<<<(NT * (HDIM / 4) + 255) / 256, 256>>>(out);
}

// round 13
// speedup vs baseline: 1.6789x; 1.0891x over previous
#include <cuda_runtime.h>
#include <cuda_fp16.h>
#include <math.h>
#include <stdint.h>

#define HDIM 1024
#define IDIM 2752
#define NE   8
#define NT   4096
#define NROUTED (2*NT)
#define NRP  9216
#define SHB  9216
#define NEP  (NRP + NT)
#define MAXTILES 72

// ---------------- scratch ----------------
__device__ int   g_counts[NE];
__device__ int   g_offp[NE];
__device__ int   g_cursor[NE];
__device__ int   g_tile_e[MAXTILES];
__device__ int   g_tile_m[MAXTILES];
__device__ int   g_topk_idx[NROUTED];
__device__ float g_topk_w[NROUTED];
__device__ int   g_perm[NRP];
__device__ float g_wgt[NRP];
__device__ int   g_entry_of[NROUTED];

__device__ __half g_x16[(size_t)NT * HDIM];
__device__ __half g_wg[(size_t)NE * IDIM * HDIM];
__device__ __half g_wu[(size_t)NE * IDIM * HDIM];
__device__ __half g_wd[(size_t)NE * HDIM * IDIM];
__device__ __half g_sg[(size_t)IDIM * HDIM];
__device__ __half g_su[(size_t)IDIM * HDIM];
__device__ __half g_sd[(size_t)HDIM * IDIM];
__device__ __half g_hm[(size_t)NEP * IDIM];
__device__ float  g_eo[(size_t)NEP * HDIM];

// ---------------- helpers ----------------
__device__ __forceinline__ uint32_t smem_u32(const void* p) {
    uint32_t a;
    asm("{ .reg .u64 t; cvta.to.shared.u64 t, %1; cvt.u32.u64 %0, t; }"
        : "=r"(a) : "l"(p));
    return a;
}
__device__ __forceinline__ void ldsm4(uint32_t* r, uint32_t a) {
    asm volatile("ldmatrix.sync.aligned.m8n8.x4.shared.b16 {%0,%1,%2,%3}, [%4];"
                 : "=r"(r[0]), "=r"(r[1]), "=r"(r[2]), "=r"(r[3]) : "r"(a));
}
__device__ __forceinline__ void mma16816(float* c, const uint32_t* a,
                                         uint32_t b0, uint32_t b1) {
    asm volatile(
        "mma.sync.aligned.m16n8k16.row.col.f32.f16.f16.f32 "
        "{%0,%1,%2,%3}, {%4,%5,%6,%7}, {%8,%9}, {%0,%1,%2,%3};"
        : "+f"(c[0]), "+f"(c[1]), "+f"(c[2]), "+f"(c[3])
        : "r"(a[0]), "r"(a[1]), "r"(a[2]), "r"(a[3]), "r"(b0), "r"(b1));
}
__device__ __forceinline__ void cpasync16(uint32_t dst, const void* src) {
    asm volatile("cp.async.cg.shared.global [%0], [%1], 16;" :: "r"(dst), "l"(src));
}
#define CP_COMMIT() asm volatile("cp.async.commit_group;" ::: "memory")
#define CP_WAIT1()  asm volatile("cp.async.wait_group 1;" ::: "memory")
#define CP_WAIT0()  asm volatile("cp.async.wait_group 0;" ::: "memory")

__device__ __forceinline__ uint32_t pack2h(__half a, __half b) {
    return ((uint32_t)__half_as_ushort(b) << 16) | __half_as_ushort(a);
}

// ---------------- small kernels ----------------
// one-shot conversion of all 7 tensors; each thread converts 8 floats.
// also zeroes g_counts (safe: finishes before gate_kernel launches)
struct ConvArgs {
    const float* src[7];
    __half*      dst[7];
    int          cum[8];   // cumulative sizes in 8-float units
};

__global__ void conv_all_kernel(ConvArgs args) {
    int idx = blockIdx.x * blockDim.x + threadIdx.x;
    if (idx < NE) g_counts[idx] = 0;
    if (idx >= args.cum[7]) return;
    int s = 0;
#pragma unroll
    for (int k = 1; k < 7; k++)
        if (idx >= args.cum[k]) s = k;
    size_t off = (size_t)(idx - args.cum[s]) * 8;
    const float4* p = (const float4*)(args.src[s] + off);
    float4 a = p[0], b = p[1];
    uint4 o;
    o.x = pack2h(__float2half_rn(a.x), __float2half_rn(a.y));
    o.y = pack2h(__float2half_rn(a.z), __float2half_rn(a.w));
    o.z = pack2h(__float2half_rn(b.x), __float2half_rn(b.y));
    o.w = pack2h(__float2half_rn(b.z), __float2half_rn(b.w));
    *(uint4*)(args.dst[s] + off) = o;
}

__global__ void gate_kernel(const float* __restrict__ x,
                            const float* __restrict__ gw) {
    int warp = (blockIdx.x * blockDim.x + threadIdx.x) >> 5;
    int lane = threadIdx.x & 31;
    if (warp >= NT) return;
    const float4* x4 = (const float4*)(x + (size_t)warp * HDIM);
    const float4* gw4 = (const float4*)gw;
    float acc[NE];
#pragma unroll
    for (int e = 0; e < NE; e++) acc[e] = 0.f;
    for (int h4 = lane; h4 < HDIM / 4; h4 += 32) {
        float4 xv = x4[h4];
#pragma unroll
        for (int e = 0; e < NE; e++) {
            float4 g = gw4[e * (HDIM / 4) + h4];
            acc[e] += xv.x * g.x + xv.y * g.y + xv.z * g.z + xv.w * g.w;
        }
    }
#pragma unroll
    for (int e = 0; e < NE; e++)
#pragma unroll
        for (int off = 16; off > 0; off >>= 1)
            acc[e] += __shfl_down_sync(0xffffffffu, acc[e], off);
    if (lane == 0) {
        float mx = acc[0];
#pragma unroll
        for (int e = 1; e < NE; e++) mx = fmaxf(mx, acc[e]);
        float p[NE], s = 0.f;
#pragma unroll
        for (int e = 0; e < NE; e++) { p[e] = expf(acc[e] - mx); s += p[e]; }
        float inv = 1.f / s;
#pragma unroll
        for (int e = 0; e < NE; e++) p[e] *= inv;
        int i1 = 0; float p1 = p[0];
#pragma unroll
        for (int e = 1; e < NE; e++) if (p[e] > p1) { p1 = p[e]; i1 = e; }
        int i2 = -1; float p2 = -1.f;
#pragma unroll
        for (int e = 0; e < NE; e++) {
            if (e == i1) continue;
            if (p[e] > p2) { p2 = p[e]; i2 = e; }
        }
        float rn = 1.f / (p1 + p2 + 1e-20f);
        g_topk_idx[2 * warp + 0] = i1;
        g_topk_idx[2 * warp + 1] = i2;
        g_topk_w[2 * warp + 0] = p1 * rn;
        g_topk_w[2 * warp + 1] = p2 * rn;
        atomicAdd(&g_counts[i1], 1);
        atomicAdd(&g_counts[i2], 1);
    }
}

__global__ void scan_kernel() {
    if (threadIdx.x == 0) {
        int s = 0, t = 0;
        for (int e = 0; e < NE; e++) {
            g_offp[e] = s;
            g_cursor[e] = s;
            int c = g_counts[e];
            int nt = (c + 127) >> 7;
            for (int m = 0; m < nt; m++) { g_tile_e[t] = e; g_tile_m[t] = m << 7; t++; }
            s += (c + 127) & ~127;
        }
        for (; t < MAXTILES; t++) g_tile_e[t] = -1;
    }
}

__global__ void scatter_kernel() {
    int i = blockIdx.x * blockDim.x + threadIdx.x;
    if (i >= NROUTED) return;
    int t = i >> 1;
    int e = g_topk_idx[i];
    int pos = atomicAdd(&g_cursor[e], 1);
    g_perm[pos] = t;
    g_wgt[pos] = g_topk_w[i];
    g_entry_of[i] = pos;
}

// ---------------- gate+up MMA GEMM ----------------
// block tile M128 x N64 (G and U), 8 warps as 4M x 2N, warp tile 32x32 both G,U
// 64 accs/thread -> occ 2; BK=64, 2-stage double buffer
#define GU_AOFF  0
#define GU_GOFF  16384
#define GU_UOFF  24576
#define GU_STAGE 32768          // A 16KB + G 8KB + U 8KB
#define GU_SMEM  (2 * GU_STAGE) // 64KB

__global__ __launch_bounds__(256, 2) void gateup_mma() {
    extern __shared__ char sm[];
    uint32_t sb = smem_u32(sm);
    int tid = threadIdx.x, wid = tid >> 5, lane = tid & 31;

    int y = blockIdx.y;
    int e, m0, base;
    bool is_shared;
    if (y >= MAXTILES) {
        is_shared = true; m0 = (y - MAXTILES) << 7; base = SHB;
    } else {
        e = g_tile_e[y];
        if (e < 0) return;
        is_shared = false; m0 = g_tile_m[y]; base = g_offp[e];
    }
    int n0 = blockIdx.x * 64;   // IDIM = 43*64 exactly

    const __half* WG = is_shared ? g_sg : g_wg + (size_t)e * IDIM * HDIM;
    const __half* WU = is_shared ? g_su : g_wu + (size_t)e * IDIM * HDIM;

    // A loads: 128 rows x 128B; thread -> row=tid>>1, 4 chunks of 16B
    int lrowA = tid >> 1, kb0 = (tid & 1) * 4;
    uint32_t swoA[4];
#pragma unroll
    for (int j = 0; j < 4; j++)
        swoA[j] = lrowA * 128 + (((kb0 + j) ^ (lrowA & 7)) << 4);
    int tok = is_shared ? (m0 + lrowA) : g_perm[base + m0 + lrowA];
    const __half* pA = g_x16 + (size_t)tok * HDIM + kb0 * 8;

    // B loads: 64 rows x 128B each for G and U; thread -> row=tid>>2, chunks {c, c+4}
    int lrowB = tid >> 2, cb0 = tid & 3;
    uint32_t swoB[2];
    swoB[0] = lrowB * 128 + ((cb0 ^ (lrowB & 7)) << 4);
    swoB[1] = lrowB * 128 + (((cb0 + 4) ^ (lrowB & 7)) << 4);
    const __half* pG = WG + (size_t)(n0 + lrowB) * HDIM + cb0 * 8;
    const __half* pU = WU + (size_t)(n0 + lrowB) * HDIM + cb0 * 8;

    auto issue = [&](int s) {
        int k0 = s * 64;
        uint32_t bb = sb + (s & 1) * GU_STAGE;
#pragma unroll
        for (int j = 0; j < 4; j++)
            cpasync16(bb + GU_AOFF + swoA[j], pA + k0 + j * 8);
        cpasync16(bb + GU_GOFF + swoB[0], pG + k0);
        cpasync16(bb + GU_GOFF + swoB[1], pG + k0 + 32);
        cpasync16(bb + GU_UOFF + swoB[0], pU + k0);
        cpasync16(bb + GU_UOFF + swoB[1], pU + k0 + 32);
    };

    // warp tiling: 4 M-warps x 2 N-warps; warp tile 32(M) x 32(N), both G and U
    int warpM = (wid >> 1) * 32;
    int warpN = (wid & 1) * 32;
    int la = lane & 15, kh = lane >> 4, x7 = la & 7;
    uint32_t rowA[2], rowB[2];
#pragma unroll
    for (int mf = 0; mf < 2; mf++) rowA[mf] = (warpM + mf * 16 + la) * 128;
#pragma unroll
    for (int s2 = 0; s2 < 2; s2++) rowB[s2] = (warpN + s2 * 16 + la) * 128;

    float aG[2][4][4], aU[2][4][4];
#pragma unroll
    for (int mf = 0; mf < 2; mf++)
#pragma unroll
        for (int nf = 0; nf < 4; nf++)
#pragma unroll
            for (int q = 0; q < 4; q++) { aG[mf][nf][q] = 0.f; aU[mf][nf][q] = 0.f; }

    issue(0); CP_COMMIT();
    for (int s = 0; s < 16; s++) {
        if (s < 15) { issue(s + 1); CP_COMMIT(); CP_WAIT1(); }
        else CP_WAIT0();
        __syncthreads();
        uint32_t bb = sb + (s & 1) * GU_STAGE;
#pragma unroll
        for (int k16 = 0; k16 < 4; k16++) {
            uint32_t ko = (uint32_t)(((k16 * 2 + kh) ^ x7) << 4);
            uint32_t A[2][4];
#pragma unroll
            for (int mf = 0; mf < 2; mf++)
                ldsm4(A[mf], bb + GU_AOFF + rowA[mf] + ko);
            uint32_t G[2][4], U[2][4];
#pragma unroll
            for (int s2 = 0; s2 < 2; s2++) {
                ldsm4(G[s2], bb + GU_GOFF + rowB[s2] + ko);
                ldsm4(U[s2], bb + GU_UOFF + rowB[s2] + ko);
            }
#pragma unroll
            for (int mf = 0; mf < 2; mf++)
#pragma unroll
                for (int s2 = 0; s2 < 2; s2++)
#pragma unroll
                    for (int j = 0; j < 2; j++) {
                        int nf = s2 * 2 + j;
                        mma16816(aG[mf][nf], A[mf], G[s2][j], G[s2][2 + j]);
                        mma16816(aU[mf][nf], A[mf], U[s2][j], U[s2][2 + j]);
                    }
        }
        __syncthreads();
    }

    // epilogue: hmid = silu(g)*u -> fp16
    int qr = lane >> 2, qc = (lane & 3) * 2;
#pragma unroll
    for (int mf = 0; mf < 2; mf++)
#pragma unroll
        for (int nf = 0; nf < 4; nf++) {
            int col = n0 + warpN + nf * 8 + qc;
            float* cg = aG[mf][nf];
            float* cu = aU[mf][nf];
            int r0 = m0 + warpM + mf * 16 + qr;
            float g0 = cg[0], g1 = cg[1], g2 = cg[2], g3 = cg[3];
            float v00 = (g0 / (1.f + expf(-g0))) * cu[0];
            float v01 = (g1 / (1.f + expf(-g1))) * cu[1];
            float v10 = (g2 / (1.f + expf(-g2))) * cu[2];
            float v11 = (g3 / (1.f + expf(-g3))) * cu[3];
            uint32_t p0 = pack2h(__float2half_rn(v00), __float2half_rn(v01));
            uint32_t p1 = pack2h(__float2half_rn(v10), __float2half_rn(v11));
            size_t o0 = (size_t)(base + r0) * IDIM + col;
            size_t o1 = o0 + (size_t)8 * IDIM;
            *(uint32_t*)(g_hm + o0) = p0;
            *(uint32_t*)(g_hm + o1) = p1;
        }
}

// ---------------- down MMA GEMM ----------------
// 2 blocks/SM: barrier + tail hiding via co-residency
#define DN_PART  16384
#define DN_STAGE (2 * DN_PART)   // A, B
#define DN_SMEM  (2 * DN_STAGE)  // 64KB

__global__ __launch_bounds__(256, 2) void down_mma() {
    extern __shared__ char sm[];
    uint32_t sb = smem_u32(sm);
    int tid = threadIdx.x, wid = tid >> 5, lane = tid & 31;

    int y = blockIdx.y;
    int e, m0, base;
    bool is_shared;
    if (y >= MAXTILES) {
        is_shared = true; m0 = (y - MAXTILES) << 7; base = SHB;
    } else {
        e = g_tile_e[y];
        if (e < 0) return;
        is_shared = false; m0 = g_tile_m[y]; base = g_offp[e];
    }
    int n0 = blockIdx.x * 128;

    const __half* WD = is_shared ? g_sd : g_wd + (size_t)e * HDIM * IDIM;

    int lrow = tid >> 1, kb0 = (tid & 1) * 4;
    uint32_t swo[4];
#pragma unroll
    for (int j = 0; j < 4; j++)
        swo[j] = lrow * 128 + (((kb0 + j) ^ (lrow & 7)) << 4);
    const __half* pA = g_hm + (size_t)(base + m0 + lrow) * IDIM + kb0 * 8;
    const __half* pB = WD + (size_t)(n0 + lrow) * IDIM + kb0 * 8;

    auto issue = [&](int s) {
        int k0 = s * 64;
        uint32_t bb = sb + (s & 1) * DN_STAGE;
#pragma unroll
        for (int j = 0; j < 4; j++) {
            cpasync16(bb + 0 * DN_PART + swo[j], pA + k0 + j * 8);
            cpasync16(bb + 1 * DN_PART + swo[j], pB + k0 + j * 8);
        }
    };

    int warpM = (wid & 1) * 64;
    int warpN = (wid >> 1) * 32;
    int la = lane & 15, kh = lane >> 4, x7 = la & 7;
    uint32_t rowA[4], rowB[2];
#pragma unroll
    for (int mf = 0; mf < 4; mf++) rowA[mf] = (warpM + mf * 16 + la) * 128;
#pragma unroll
    for (int s2 = 0; s2 < 2; s2++) rowB[s2] = (warpN + s2 * 16 + la) * 128;

    float acc[4][4][4];
#pragma unroll
    for (int mf = 0; mf < 4; mf++)
#pragma unroll
        for (int nf = 0; nf < 4; nf++)
#pragma unroll
            for (int q = 0; q < 4; q++) acc[mf][nf][q] = 0.f;

    const int S = IDIM / 64;   // 43
    issue(0); CP_COMMIT();
    for (int s = 0; s < S; s++) {
        if (s < S - 1) { issue(s + 1); CP_COMMIT(); CP_WAIT1(); }
        else CP_WAIT0();
        __syncthreads();
        uint32_t bb = sb + (s & 1) * DN_STAGE;
#pragma unroll
        for (int k16 = 0; k16 < 4; k16++) {
            uint32_t ko = (uint32_t)(((k16 * 2 + kh) ^ x7) << 4);
            uint32_t A[4][4];
#pragma unroll
            for (int mf = 0; mf < 4; mf++)
                ldsm4(A[mf], bb + 0 * DN_PART + rowA[mf] + ko);
            uint32_t B[2][4];
#pragma unroll
            for (int s2 = 0; s2 < 2; s2++)
                ldsm4(B[s2], bb + 1 * DN_PART + rowB[s2] + ko);
#pragma unroll
            for (int mf = 0; mf < 4; mf++)
#pragma unroll
                for (int s2 = 0; s2 < 2; s2++)
#pragma unroll
                    for (int j = 0; j < 2; j++) {
                        int nf = s2 * 2 + j;
                        mma16816(acc[mf][nf], A[mf], B[s2][j], B[s2][2 + j]);
                    }
        }
        __syncthreads();
    }

    int qr = lane >> 2, qc = (lane & 3) * 2;
#pragma unroll
    for (int mf = 0; mf < 4; mf++) {
        int r0 = m0 + warpM + mf * 16 + qr;
        float w0 = is_shared ? 1.f : g_wgt[base + r0];
        float w1 = is_shared ? 1.f : g_wgt[base + r0 + 8];
#pragma unroll
        for (int nf = 0; nf < 4; nf++) {
            int col = n0 + warpN + nf * 8 + qc;
            float* c = acc[mf][nf];
            size_t o0 = (size_t)(base + r0) * HDIM + col;
            size_t o1 = o0 + (size_t)8 * HDIM;
            float2 v0 = make_float2(c[0] * w0, c[1] * w0);
            float2 v1 = make_float2(c[2] * w1, c[3] * w1);
            *(float2*)(g_eo + o0) = v0;
            *(float2*)(g_eo + o1) = v1;
        }
    }
}

// ---------------- combine ----------------
__global__ void combine_kernel(float* __restrict__ out) {
    int idx = blockIdx.x * blockDim.x + threadIdx.x;
    const int HC = HDIM / 4;
    if (idx >= NT * HC) return;
    int t = idx / HC;
    int c = idx - t * HC;
    const float4* eo4 = (const float4*)g_eo;
    int e1 = g_entry_of[2 * t + 0];
    int e2 = g_entry_of[2 * t + 1];
    float4 a = eo4[(size_t)e1 * HC + c];
    float4 b = eo4[(size_t)e2 * HC + c];
    float4 s = eo4[(size_t)(SHB + t) * HC + c];
    float4 r;
    r.x = a.x + b.x + s.x;
    r.y = a.y + b.y + s.y;
    r.z = a.z + b.z + s.z;
    r.w = a.w + b.w + s.w;
    ((float4*)out)[idx] = r;
}

// ---------------- launch ----------------
extern "C" void kernel_launch(void* const* d_in, const int* in_sizes, int n_in,
                              void* d_out, int out_size) {
    const float* x       = (const float*)d_in[0];
    const float* gate_w  = (const float*)d_in[1];
    const float* w_gate  = (const float*)d_in[2];
    const float* w_up    = (const float*)d_in[3];
    const float* w_down  = (const float*)d_in[4];
    const float* ws_gate = (const float*)d_in[5];
    const float* ws_up   = (const float*)d_in[6];
    const float* ws_down = (const float*)d_in[7];
    float* out = (float*)d_out;

    cudaFuncSetAttribute(gateup_mma, cudaFuncAttributeMaxDynamicSharedMemorySize, GU_SMEM);
    cudaFuncSetAttribute(down_mma,   cudaFuncAttributeMaxDynamicSharedMemorySize, DN_SMEM);

    __half *x16, *wg, *wu, *wd, *sg, *su, *sd;
    cudaGetSymbolAddress((void**)&x16, g_x16);
    cudaGetSymbolAddress((void**)&wg, g_wg); cudaGetSymbolAddress((void**)&wu, g_wu);
    cudaGetSymbolAddress((void**)&wd, g_wd);
    cudaGetSymbolAddress((void**)&sg, g_sg); cudaGetSymbolAddress((void**)&su, g_su);
    cudaGetSymbolAddress((void**)&sd, g_sd);

    // segment table (units of 8 floats)
    ConvArgs ca;
    ca.src[0] = x;       ca.dst[0] = x16;
    ca.src[1] = w_gate;  ca.dst[1] = wg;
    ca.src[2] = w_up;    ca.dst[2] = wu;
    ca.src[3] = w_down;  ca.dst[3] = wd;
    ca.src[4] = ws_gate; ca.dst[4] = sg;
    ca.src[5] = ws_up;   ca.dst[5] = su;
    ca.src[6] = ws_down; ca.dst[6] = sd;
    int sz8[7] = {
        NT * HDIM / 8,
        NE * IDIM * HDIM / 8, NE * IDIM * HDIM / 8, NE * IDIM * HDIM / 8,
        IDIM * HDIM / 8, IDIM * HDIM / 8, IDIM * HDIM / 8
    };
    ca.cum[0] = 0;
    for (int i = 0; i < 7; i++) ca.cum[i + 1] = ca.cum[i] + sz8[i];
    int total = ca.cum[7];

    conv_all_kernel<<<(total + 255) / 256, 256>>>(ca);
    gate_kernel<<<NT / 8, 256>>>(x, gate_w);
    scan_kernel<<<1, 32>>>();
    scatter_kernel<<<(NROUTED + 255) / 256, 256>>>();

    gateup_mma<<<dim3(IDIM / 64, MAXTILES + NT / 128, 1), 256, GU_SMEM>>>();
    down_mma<<<dim3(HDIM / 128, MAXTILES + NT / 128, 1), 256, DN_SMEM>>>();
    combine_kernel<<<(NT * (HDIM / 4) + 255) / 256, 256>>>(out);
}

// round 14
// speedup vs baseline: 1.6790x; 1.0000x over previous
#include <cuda_runtime.h>
#include <cuda_fp16.h>
#include <math.h>
#include <stdint.h>

#define HDIM 1024
#define IDIM 2752
#define NE   8
#define NT   4096
#define NROUTED (2*NT)
#define NRP  9216
#define SHB  9216
#define NEP  (NRP + NT)
#define MAXTILES 72
#define GATE_BLOCKS (NT / 8)   // 512 blocks, 8 warps each, 1 warp per token

// ---------------- scratch ----------------
__device__ int   g_offp[NE];
__device__ int   g_cursor[NE];
__device__ int   g_tile_e[MAXTILES];
__device__ int   g_tile_m[MAXTILES];
__device__ int   g_topk_idx[NROUTED];
__device__ float g_topk_w[NROUTED];
__device__ int   g_perm[NRP];
__device__ float g_wgt[NRP];
__device__ int   g_entry_of[NROUTED];

__device__ __half g_x16[(size_t)NT * HDIM];
__device__ __half g_wg[(size_t)NE * IDIM * HDIM];
__device__ __half g_wu[(size_t)NE * IDIM * HDIM];
__device__ __half g_wd[(size_t)NE * HDIM * IDIM];
__device__ __half g_sg[(size_t)IDIM * HDIM];
__device__ __half g_su[(size_t)IDIM * HDIM];
__device__ __half g_sd[(size_t)HDIM * IDIM];
__device__ __half g_hm[(size_t)NEP * IDIM];
__device__ float  g_eo[(size_t)NEP * HDIM];

// ---------------- helpers ----------------
__device__ __forceinline__ uint32_t smem_u32(const void* p) {
    uint32_t a;
    asm("{ .reg .u64 t; cvta.to.shared.u64 t, %1; cvt.u32.u64 %0, t; }"
        : "=r"(a) : "l"(p));
    return a;
}
__device__ __forceinline__ void ldsm4(uint32_t* r, uint32_t a) {
    asm volatile("ldmatrix.sync.aligned.m8n8.x4.shared.b16 {%0,%1,%2,%3}, [%4];"
                 : "=r"(r[0]), "=r"(r[1]), "=r"(r[2]), "=r"(r[3]) : "r"(a));
}
__device__ __forceinline__ void mma16816(float* c, const uint32_t* a,
                                         uint32_t b0, uint32_t b1) {
    asm volatile(
        "mma.sync.aligned.m16n8k16.row.col.f32.f16.f16.f32 "
        "{%0,%1,%2,%3}, {%4,%5,%6,%7}, {%8,%9}, {%0,%1,%2,%3};"
        : "+f"(c[0]), "+f"(c[1]), "+f"(c[2]), "+f"(c[3])
        : "r"(a[0]), "r"(a[1]), "r"(a[2]), "r"(a[3]), "r"(b0), "r"(b1));
}
__device__ __forceinline__ void cpasync16(uint32_t dst, const void* src) {
    asm volatile("cp.async.cg.shared.global [%0], [%1], 16;" :: "r"(dst), "l"(src));
}
#define CP_COMMIT() asm volatile("cp.async.commit_group;" ::: "memory")
#define CP_WAIT1()  asm volatile("cp.async.wait_group 1;" ::: "memory")
#define CP_WAIT0()  asm volatile("cp.async.wait_group 0;" ::: "memory")

__device__ __forceinline__ uint32_t pack2h(__half a, __half b) {
    return ((uint32_t)__half_as_ushort(b) << 16) | __half_as_ushort(a);
}

// ---------------- fused gate + conversion kernel ----------------
// blocks [0, GATE_BLOCKS): router gating, 1 warp per token (reads fp32 x, gate_w)
// blocks [GATE_BLOCKS, ...): fp32 -> fp16 conversion of all 7 tensors
struct ConvArgs {
    const float* src[7];
    __half*      dst[7];
    int          cum[8];   // cumulative sizes in 8-float units
};

__global__ void conv_gate_kernel(ConvArgs args,
                                 const float* __restrict__ x,
                                 const float* __restrict__ gw) {
    if (blockIdx.x < GATE_BLOCKS) {
        int warp = blockIdx.x * 8 + (threadIdx.x >> 5);
        int lane = threadIdx.x & 31;
        const float4* x4 = (const float4*)(x + (size_t)warp * HDIM);
        const float4* gw4 = (const float4*)gw;
        float acc[NE];
#pragma unroll
        for (int e = 0; e < NE; e++) acc[e] = 0.f;
        for (int h4 = lane; h4 < HDIM / 4; h4 += 32) {
            float4 xv = x4[h4];
#pragma unroll
            for (int e = 0; e < NE; e++) {
                float4 g = gw4[e * (HDIM / 4) + h4];
                acc[e] += xv.x * g.x + xv.y * g.y + xv.z * g.z + xv.w * g.w;
            }
        }
#pragma unroll
        for (int e = 0; e < NE; e++)
#pragma unroll
            for (int off = 16; off > 0; off >>= 1)
                acc[e] += __shfl_down_sync(0xffffffffu, acc[e], off);
        if (lane == 0) {
            float mx = acc[0];
#pragma unroll
            for (int e = 1; e < NE; e++) mx = fmaxf(mx, acc[e]);
            float p[NE], s = 0.f;
#pragma unroll
            for (int e = 0; e < NE; e++) { p[e] = expf(acc[e] - mx); s += p[e]; }
            float inv = 1.f / s;
#pragma unroll
            for (int e = 0; e < NE; e++) p[e] *= inv;
            int i1 = 0; float p1 = p[0];
#pragma unroll
            for (int e = 1; e < NE; e++) if (p[e] > p1) { p1 = p[e]; i1 = e; }
            int i2 = -1; float p2 = -1.f;
#pragma unroll
            for (int e = 0; e < NE; e++) {
                if (e == i1) continue;
                if (p[e] > p2) { p2 = p[e]; i2 = e; }
            }
            float rn = 1.f / (p1 + p2 + 1e-20f);
            g_topk_idx[2 * warp + 0] = i1;
            g_topk_idx[2 * warp + 1] = i2;
            g_topk_w[2 * warp + 0] = p1 * rn;
            g_topk_w[2 * warp + 1] = p2 * rn;
        }
        return;
    }
    int idx = (blockIdx.x - GATE_BLOCKS) * blockDim.x + threadIdx.x;
    if (idx >= args.cum[7]) return;
    int s = 0;
#pragma unroll
    for (int k = 1; k < 7; k++)
        if (idx >= args.cum[k]) s = k;
    size_t off = (size_t)(idx - args.cum[s]) * 8;
    const float4* p = (const float4*)(args.src[s] + off);
    float4 a = p[0], b = p[1];
    uint4 o;
    o.x = pack2h(__float2half_rn(a.x), __float2half_rn(a.y));
    o.y = pack2h(__float2half_rn(a.z), __float2half_rn(a.w));
    o.z = pack2h(__float2half_rn(b.x), __float2half_rn(b.y));
    o.w = pack2h(__float2half_rn(b.z), __float2half_rn(b.w));
    *(uint4*)(args.dst[s] + off) = o;
}

// ---------------- scan: recount experts + offsets + tile list ----------------
__global__ void scan_kernel() {
    __shared__ int cnt[NE];
    int tid = threadIdx.x;
    if (tid < NE) cnt[tid] = 0;
    __syncthreads();
    for (int i = tid; i < NROUTED; i += blockDim.x)
        atomicAdd(&cnt[g_topk_idx[i]], 1);
    __syncthreads();
    if (tid == 0) {
        int s = 0, t = 0;
        for (int e = 0; e < NE; e++) {
            g_offp[e] = s;
            g_cursor[e] = s;
            int c = cnt[e];
            int nt = (c + 127) >> 7;
            for (int m = 0; m < nt; m++) { g_tile_e[t] = e; g_tile_m[t] = m << 7; t++; }
            s += (c + 127) & ~127;
        }
        for (; t < MAXTILES; t++) g_tile_e[t] = -1;
    }
}

__global__ void scatter_kernel() {
    int i = blockIdx.x * blockDim.x + threadIdx.x;
    if (i >= NROUTED) return;
    int t = i >> 1;
    int e = g_topk_idx[i];
    int pos = atomicAdd(&g_cursor[e], 1);
    g_perm[pos] = t;
    g_wgt[pos] = g_topk_w[i];
    g_entry_of[i] = pos;
}

// ---------------- gate+up MMA GEMM ----------------
// block tile M128 x N64 (G and U), 8 warps as 4M x 2N, warp tile 32x32 both G,U
// 64 accs/thread -> occ 2; BK=64, 2-stage double buffer
#define GU_AOFF  0
#define GU_GOFF  16384
#define GU_UOFF  24576
#define GU_STAGE 32768          // A 16KB + G 8KB + U 8KB
#define GU_SMEM  (2 * GU_STAGE) // 64KB

__global__ __launch_bounds__(256, 2) void gateup_mma() {
    extern __shared__ char sm[];
    uint32_t sb = smem_u32(sm);
    int tid = threadIdx.x, wid = tid >> 5, lane = tid & 31;

    int y = blockIdx.y;
    int e, m0, base;
    bool is_shared;
    if (y >= MAXTILES) {
        is_shared = true; m0 = (y - MAXTILES) << 7; base = SHB;
    } else {
        e = g_tile_e[y];
        if (e < 0) return;
        is_shared = false; m0 = g_tile_m[y]; base = g_offp[e];
    }
    int n0 = blockIdx.x * 64;   // IDIM = 43*64 exactly

    const __half* WG = is_shared ? g_sg : g_wg + (size_t)e * IDIM * HDIM;
    const __half* WU = is_shared ? g_su : g_wu + (size_t)e * IDIM * HDIM;

    // A loads: 128 rows x 128B; thread -> row=tid>>1, 4 chunks of 16B
    int lrowA = tid >> 1, kb0 = (tid & 1) * 4;
    uint32_t swoA[4];
#pragma unroll
    for (int j = 0; j < 4; j++)
        swoA[j] = lrowA * 128 + (((kb0 + j) ^ (lrowA & 7)) << 4);
    int tok = is_shared ? (m0 + lrowA) : g_perm[base + m0 + lrowA];
    const __half* pA = g_x16 + (size_t)tok * HDIM + kb0 * 8;

    // B loads: 64 rows x 128B each for G and U; thread -> row=tid>>2, chunks {c, c+4}
    int lrowB = tid >> 2, cb0 = tid & 3;
    uint32_t swoB[2];
    swoB[0] = lrowB * 128 + ((cb0 ^ (lrowB & 7)) << 4);
    swoB[1] = lrowB * 128 + (((cb0 + 4) ^ (lrowB & 7)) << 4);
    const __half* pG = WG + (size_t)(n0 + lrowB) * HDIM + cb0 * 8;
    const __half* pU = WU + (size_t)(n0 + lrowB) * HDIM + cb0 * 8;

    auto issue = [&](int s) {
        int k0 = s * 64;
        uint32_t bb = sb + (s & 1) * GU_STAGE;
#pragma unroll
        for (int j = 0; j < 4; j++)
            cpasync16(bb + GU_AOFF + swoA[j], pA + k0 + j * 8);
        cpasync16(bb + GU_GOFF + swoB[0], pG + k0);
        cpasync16(bb + GU_GOFF + swoB[1], pG + k0 + 32);
        cpasync16(bb + GU_UOFF + swoB[0], pU + k0);
        cpasync16(bb + GU_UOFF + swoB[1], pU + k0 + 32);
    };

    // warp tiling: 4 M-warps x 2 N-warps; warp tile 32(M) x 32(N), both G and U
    int warpM = (wid >> 1) * 32;
    int warpN = (wid & 1) * 32;
    int la = lane & 15, kh = lane >> 4, x7 = la & 7;
    uint32_t rowA[2], rowB[2];
#pragma unroll
    for (int mf = 0; mf < 2; mf++) rowA[mf] = (warpM + mf * 16 + la) * 128;
#pragma unroll
    for (int s2 = 0; s2 < 2; s2++) rowB[s2] = (warpN + s2 * 16 + la) * 128;

    float aG[2][4][4], aU[2][4][4];
#pragma unroll
    for (int mf = 0; mf < 2; mf++)
#pragma unroll
        for (int nf = 0; nf < 4; nf++)
#pragma unroll
            for (int q = 0; q < 4; q++) { aG[mf][nf][q] = 0.f; aU[mf][nf][q] = 0.f; }

    issue(0); CP_COMMIT();
    for (int s = 0; s < 16; s++) {
        if (s < 15) { issue(s + 1); CP_COMMIT(); CP_WAIT1(); }
        else CP_WAIT0();
        __syncthreads();
        uint32_t bb = sb + (s & 1) * GU_STAGE;
#pragma unroll
        for (int k16 = 0; k16 < 4; k16++) {
            uint32_t ko = (uint32_t)(((k16 * 2 + kh) ^ x7) << 4);
            uint32_t A[2][4];
#pragma unroll
            for (int mf = 0; mf < 2; mf++)
                ldsm4(A[mf], bb + GU_AOFF + rowA[mf] + ko);
            uint32_t G[2][4], U[2][4];
#pragma unroll
            for (int s2 = 0; s2 < 2; s2++) {
                ldsm4(G[s2], bb + GU_GOFF + rowB[s2] + ko);
                ldsm4(U[s2], bb + GU_UOFF + rowB[s2] + ko);
            }
#pragma unroll
            for (int mf = 0; mf < 2; mf++)
#pragma unroll
                for (int s2 = 0; s2 < 2; s2++)
#pragma unroll
                    for (int j = 0; j < 2; j++) {
                        int nf = s2 * 2 + j;
                        mma16816(aG[mf][nf], A[mf], G[s2][j], G[s2][2 + j]);
                        mma16816(aU[mf][nf], A[mf], U[s2][j], U[s2][2 + j]);
                    }
        }
        __syncthreads();
    }

    // epilogue: hmid = silu(g)*u -> fp16
    int qr = lane >> 2, qc = (lane & 3) * 2;
#pragma unroll
    for (int mf = 0; mf < 2; mf++)
#pragma unroll
        for (int nf = 0; nf < 4; nf++) {
            int col = n0 + warpN + nf * 8 + qc;
            float* cg = aG[mf][nf];
            float* cu = aU[mf][nf];
            int r0 = m0 + warpM + mf * 16 + qr;
            float g0 = cg[0], g1 = cg[1], g2 = cg[2], g3 = cg[3];
            float v00 = (g0 / (1.f + expf(-g0))) * cu[0];
            float v01 = (g1 / (1.f + expf(-g1))) * cu[1];
            float v10 = (g2 / (1.f + expf(-g2))) * cu[2];
            float v11 = (g3 / (1.f + expf(-g3))) * cu[3];
            uint32_t p0 = pack2h(__float2half_rn(v00), __float2half_rn(v01));
            uint32_t p1 = pack2h(__float2half_rn(v10), __float2half_rn(v11));
            size_t o0 = (size_t)(base + r0) * IDIM + col;
            size_t o1 = o0 + (size_t)8 * IDIM;
            *(uint32_t*)(g_hm + o0) = p0;
            *(uint32_t*)(g_hm + o1) = p1;
        }
}

// ---------------- down MMA GEMM ----------------
// 2 blocks/SM: barrier + tail hiding via co-residency
#define DN_PART  16384
#define DN_STAGE (2 * DN_PART)   // A, B
#define DN_SMEM  (2 * DN_STAGE)  // 64KB

__global__ __launch_bounds__(256, 2) void down_mma() {
    extern __shared__ char sm[];
    uint32_t sb = smem_u32(sm);
    int tid = threadIdx.x, wid = tid >> 5, lane = tid & 31;

    int y = blockIdx.y;
    int e, m0, base;
    bool is_shared;
    if (y >= MAXTILES) {
        is_shared = true; m0 = (y - MAXTILES) << 7; base = SHB;
    } else {
        e = g_tile_e[y];
        if (e < 0) return;
        is_shared = false; m0 = g_tile_m[y]; base = g_offp[e];
    }
    int n0 = blockIdx.x * 128;

    const __half* WD = is_shared ? g_sd : g_wd + (size_t)e * HDIM * IDIM;

    int lrow = tid >> 1, kb0 = (tid & 1) * 4;
    uint32_t swo[4];
#pragma unroll
    for (int j = 0; j < 4; j++)
        swo[j] = lrow * 128 + (((kb0 + j) ^ (lrow & 7)) << 4);
    const __half* pA = g_hm + (size_t)(base + m0 + lrow) * IDIM + kb0 * 8;
    const __half* pB = WD + (size_t)(n0 + lrow) * IDIM + kb0 * 8;

    auto issue = [&](int s) {
        int k0 = s * 64;
        uint32_t bb = sb + (s & 1) * DN_STAGE;
#pragma unroll
        for (int j = 0; j < 4; j++) {
            cpasync16(bb + 0 * DN_PART + swo[j], pA + k0 + j * 8);
            cpasync16(bb + 1 * DN_PART + swo[j], pB + k0 + j * 8);
        }
    };

    int warpM = (wid & 1) * 64;
    int warpN = (wid >> 1) * 32;
    int la = lane & 15, kh = lane >> 4, x7 = la & 7;
    uint32_t rowA[4], rowB[2];
#pragma unroll
    for (int mf = 0; mf < 4; mf++) rowA[mf] = (warpM + mf * 16 + la) * 128;
#pragma unroll
    for (int s2 = 0; s2 < 2; s2++) rowB[s2] = (warpN + s2 * 16 + la) * 128;

    float acc[4][4][4];
#pragma unroll
    for (int mf = 0; mf < 4; mf++)
#pragma unroll
        for (int nf = 0; nf < 4; nf++)
#pragma unroll
            for (int q = 0; q < 4; q++) acc[mf][nf][q] = 0.f;

    const int S = IDIM / 64;   // 43
    issue(0); CP_COMMIT();
    for (int s = 0; s < S; s++) {
        if (s < S - 1) { issue(s + 1); CP_COMMIT(); CP_WAIT1(); }
        else CP_WAIT0();
        __syncthreads();
        uint32_t bb = sb + (s & 1) * DN_STAGE;
#pragma unroll
        for (int k16 = 0; k16 < 4; k16++) {
            uint32_t ko = (uint32_t)(((k16 * 2 + kh) ^ x7) << 4);
            uint32_t A[4][4];
#pragma unroll
            for (int mf = 0; mf < 4; mf++)
                ldsm4(A[mf], bb + 0 * DN_PART + rowA[mf] + ko);
            uint32_t B[2][4];
#pragma unroll
            for (int s2 = 0; s2 < 2; s2++)
                ldsm4(B[s2], bb + 1 * DN_PART + rowB[s2] + ko);
#pragma unroll
            for (int mf = 0; mf < 4; mf++)
#pragma unroll
                for (int s2 = 0; s2 < 2; s2++)
#pragma unroll
                    for (int j = 0; j < 2; j++) {
                        int nf = s2 * 2 + j;
                        mma16816(acc[mf][nf], A[mf], B[s2][j], B[s2][2 + j]);
                    }
        }
        __syncthreads();
    }

    int qr = lane >> 2, qc = (lane & 3) * 2;
#pragma unroll
    for (int mf = 0; mf < 4; mf++) {
        int r0 = m0 + warpM + mf * 16 + qr;
        float w0 = is_shared ? 1.f : g_wgt[base + r0];
        float w1 = is_shared ? 1.f : g_wgt[base + r0 + 8];
#pragma unroll
        for (int nf = 0; nf < 4; nf++) {
            int col = n0 + warpN + nf * 8 + qc;
            float* c = acc[mf][nf];
            size_t o0 = (size_t)(base + r0) * HDIM + col;
            size_t o1 = o0 + (size_t)8 * HDIM;
            float2 v0 = make_float2(c[0] * w0, c[1] * w0);
            float2 v1 = make_float2(c[2] * w1, c[3] * w1);
            *(float2*)(g_eo + o0) = v0;
            *(float2*)(g_eo + o1) = v1;
        }
    }
}

// ---------------- combine ----------------
__global__ void combine_kernel(float* __restrict__ out) {
    int idx = blockIdx.x * blockDim.x + threadIdx.x;
    const int HC = HDIM / 4;
    if (idx >= NT * HC) return;
    int t = idx / HC;
    int c = idx - t * HC;
    const float4* eo4 = (const float4*)g_eo;
    int e1 = g_entry_of[2 * t + 0];
    int e2 = g_entry_of[2 * t + 1];
    float4 a = eo4[(size_t)e1 * HC + c];
    float4 b = eo4[(size_t)e2 * HC + c];
    float4 s = eo4[(size_t)(SHB + t) * HC + c];
    float4 r;
    r.x = a.x + b.x + s.x;
    r.y = a.y + b.y + s.y;
    r.z = a.z + b.z + s.z;
    r.w = a.w + b.w + s.w;
    ((float4*)out)[idx] = r;
}

// ---------------- launch ----------------
extern "C" void kernel_launch(void* const* d_in, const int* in_sizes, int n_in,
                              void* d_out, int out_size) {
    const float* x       = (const float*)d_in[0];
    const float* gate_w  = (const float*)d_in[1];
    const float* w_gate  = (const float*)d_in[2];
    const float* w_up    = (const float*)d_in[3];
    const float* w_down  = (const float*)d_in[4];
    const float* ws_gate = (const float*)d_in[5];
    const float* ws_up   = (const float*)d_in[6];
    const float* ws_down = (const float*)d_in[7];
    float* out = (float*)d_out;

    cudaFuncSetAttribute(gateup_mma, cudaFuncAttributeMaxDynamicSharedMemorySize, GU_SMEM);
    cudaFuncSetAttribute(down_mma,   cudaFuncAttributeMaxDynamicSharedMemorySize, DN_SMEM);

    __half *x16, *wg, *wu, *wd, *sg, *su, *sd;
    cudaGetSymbolAddress((void**)&x16, g_x16);
    cudaGetSymbolAddress((void**)&wg, g_wg); cudaGetSymbolAddress((void**)&wu, g_wu);
    cudaGetSymbolAddress((void**)&wd, g_wd);
    cudaGetSymbolAddress((void**)&sg, g_sg); cudaGetSymbolAddress((void**)&su, g_su);
    cudaGetSymbolAddress((void**)&sd, g_sd);

    // segment table (units of 8 floats)
    ConvArgs ca;
    ca.src[0] = x;       ca.dst[0] = x16;
    ca.src[1] = w_gate;  ca.dst[1] = wg;
    ca.src[2] = w_up;    ca.dst[2] = wu;
    ca.src[3] = w_down;  ca.dst[3] = wd;
    ca.src[4] = ws_gate; ca.dst[4] = sg;
    ca.src[5] = ws_up;   ca.dst[5] = su;
    ca.src[6] = ws_down; ca.dst[6] = sd;
    int sz8[7] = {
        NT * HDIM / 8,
        NE * IDIM * HDIM / 8, NE * IDIM * HDIM / 8, NE * IDIM * HDIM / 8,
        IDIM * HDIM / 8, IDIM * HDIM / 8, IDIM * HDIM / 8
    };
    ca.cum[0] = 0;
    for (int i = 0; i < 7; i++) ca.cum[i + 1] = ca.cum[i] + sz8[i];
    int total = ca.cum[7];

    int conv_blocks = (total + 255) / 256;
    conv_gate_kernel<<<GATE_BLOCKS + conv_blocks, 256>>>(ca, x, gate_w);
    scan_kernel<<<1, 256>>>();
    scatter_kernel<<<(NROUTED + 255) / 256, 256>>>();

    gateup_mma<<<dim3(IDIM / 64, MAXTILES + NT / 128, 1), 256, GU_SMEM>>>();
    down_mma<<<dim3(HDIM / 128, MAXTILES + NT / 128, 1), 256, DN_SMEM>>>();
    combine_kernel<<<(NT * (HDIM / 4) + 255) / 256, 256>>>(out);
}

// round 15
// speedup vs baseline: 1.6945x; 1.0093x over previous
#include <cuda_runtime.h>
#include <cuda_fp16.h>
#include <math.h>
#include <stdint.h>

#define HDIM 1024
#define IDIM 2752
#define NE   8
#define NT   4096
#define NROUTED (2*NT)
#define NRP  9216
#define SHB  9216
#define NEP  (NRP + NT)
#define MAXTILES 72
#define GATE_BLOCKS (NT / 8)

// ---------------- scratch ----------------
__device__ int   g_offp[NE];
__device__ int   g_cursor[NE];
__device__ int   g_tile_e[MAXTILES];
__device__ int   g_tile_m[MAXTILES];
__device__ int   g_topk_idx[NROUTED];
__device__ float g_topk_w[NROUTED];
__device__ int   g_perm[NRP];
__device__ float g_wgt[NRP];
__device__ int   g_entry_of[NROUTED];

__device__ __half g_x16[(size_t)NT * HDIM];
__device__ __half g_wg[(size_t)NE * IDIM * HDIM];
__device__ __half g_wu[(size_t)NE * IDIM * HDIM];
__device__ __half g_wd[(size_t)NE * HDIM * IDIM];
__device__ __half g_sg[(size_t)IDIM * HDIM];
__device__ __half g_su[(size_t)IDIM * HDIM];
__device__ __half g_sd[(size_t)HDIM * IDIM];
__device__ __half g_hm[(size_t)NEP * IDIM];
__device__ float  g_eo[(size_t)NEP * HDIM];

// ---------------- helpers ----------------
__device__ __forceinline__ uint32_t smem_u32(const void* p) {
    uint32_t a;
    asm("{ .reg .u64 t; cvta.to.shared.u64 t, %1; cvt.u32.u64 %0, t; }"
        : "=r"(a) : "l"(p));
    return a;
}
__device__ __forceinline__ void ldsm4(uint32_t* r, uint32_t a) {
    asm volatile("ldmatrix.sync.aligned.m8n8.x4.shared.b16 {%0,%1,%2,%3}, [%4];"
                 : "=r"(r[0]), "=r"(r[1]), "=r"(r[2]), "=r"(r[3]) : "r"(a));
}
__device__ __forceinline__ void mma16816(float* c, const uint32_t* a,
                                         uint32_t b0, uint32_t b1) {
    asm volatile(
        "mma.sync.aligned.m16n8k16.row.col.f32.f16.f16.f32 "
        "{%0,%1,%2,%3}, {%4,%5,%6,%7}, {%8,%9}, {%0,%1,%2,%3};"
        : "+f"(c[0]), "+f"(c[1]), "+f"(c[2]), "+f"(c[3])
        : "r"(a[0]), "r"(a[1]), "r"(a[2]), "r"(a[3]), "r"(b0), "r"(b1));
}
__device__ __forceinline__ void cpasync16(uint32_t dst, const void* src) {
    asm volatile("cp.async.cg.shared.global [%0], [%1], 16;" :: "r"(dst), "l"(src));
}
#define CP_COMMIT() asm volatile("cp.async.commit_group;" ::: "memory")
#define CP_WAIT1()  asm volatile("cp.async.wait_group 1;" ::: "memory")
#define CP_WAIT0()  asm volatile("cp.async.wait_group 0;" ::: "memory")

__device__ __forceinline__ uint32_t pack2h(__half a, __half b) {
    return ((uint32_t)__half_as_ushort(b) << 16) | __half_as_ushort(a);
}

// ---------------- fused gate + conversion kernel ----------------
struct ConvArgs {
    const float* src[7];
    __half*      dst[7];
    int          cum[8];
};

__global__ void conv_gate_kernel(ConvArgs args,
                                 const float* __restrict__ x,
                                 const float* __restrict__ gw) {
    if (blockIdx.x < GATE_BLOCKS) {
        int warp = blockIdx.x * 8 + (threadIdx.x >> 5);
        int lane = threadIdx.x & 31;
        const float4* x4 = (const float4*)(x + (size_t)warp * HDIM);
        const float4* gw4 = (const float4*)gw;
        float acc[NE];
#pragma unroll
        for (int e = 0; e < NE; e++) acc[e] = 0.f;
        for (int h4 = lane; h4 < HDIM / 4; h4 += 32) {
            float4 xv = x4[h4];
#pragma unroll
            for (int e = 0; e < NE; e++) {
                float4 g = gw4[e * (HDIM / 4) + h4];
                acc[e] += xv.x * g.x + xv.y * g.y + xv.z * g.z + xv.w * g.w;
            }
        }
#pragma unroll
        for (int e = 0; e < NE; e++)
#pragma unroll
            for (int off = 16; off > 0; off >>= 1)
                acc[e] += __shfl_down_sync(0xffffffffu, acc[e], off);
        if (lane == 0) {
            float mx = acc[0];
#pragma unroll
            for (int e = 1; e < NE; e++) mx = fmaxf(mx, acc[e]);
            float p[NE], s = 0.f;
#pragma unroll
            for (int e = 0; e < NE; e++) { p[e] = expf(acc[e] - mx); s += p[e]; }
            float inv = 1.f / s;
#pragma unroll
            for (int e = 0; e < NE; e++) p[e] *= inv;
            int i1 = 0; float p1 = p[0];
#pragma unroll
            for (int e = 1; e < NE; e++) if (p[e] > p1) { p1 = p[e]; i1 = e; }
            int i2 = -1; float p2 = -1.f;
#pragma unroll
            for (int e = 0; e < NE; e++) {
                if (e == i1) continue;
                if (p[e] > p2) { p2 = p[e]; i2 = e; }
            }
            float rn = 1.f / (p1 + p2 + 1e-20f);
            g_topk_idx[2 * warp + 0] = i1;
            g_topk_idx[2 * warp + 1] = i2;
            g_topk_w[2 * warp + 0] = p1 * rn;
            g_topk_w[2 * warp + 1] = p2 * rn;
        }
        return;
    }
    int idx = (blockIdx.x - GATE_BLOCKS) * blockDim.x + threadIdx.x;
    if (idx >= args.cum[7]) return;
    int s = 0;
#pragma unroll
    for (int k = 1; k < 7; k++)
        if (idx >= args.cum[k]) s = k;
    size_t off = (size_t)(idx - args.cum[s]) * 8;
    const float4* p = (const float4*)(args.src[s] + off);
    float4 a = p[0], b = p[1];
    uint4 o;
    o.x = pack2h(__float2half_rn(a.x), __float2half_rn(a.y));
    o.y = pack2h(__float2half_rn(a.z), __float2half_rn(a.w));
    o.z = pack2h(__float2half_rn(b.x), __float2half_rn(b.y));
    o.w = pack2h(__float2half_rn(b.z), __float2half_rn(b.w));
    *(uint4*)(args.dst[s] + off) = o;
}

// ---------------- scan ----------------
__global__ void scan_kernel() {
    __shared__ int cnt[NE];
    int tid = threadIdx.x;
    if (tid < NE) cnt[tid] = 0;
    __syncthreads();
    for (int i = tid; i < NROUTED; i += blockDim.x)
        atomicAdd(&cnt[g_topk_idx[i]], 1);
    __syncthreads();
    if (tid == 0) {
        int s = 0, t = 0;
        for (int e = 0; e < NE; e++) {
            g_offp[e] = s;
            g_cursor[e] = s;
            int c = cnt[e];
            int nt = (c + 127) >> 7;
            for (int m = 0; m < nt; m++) { g_tile_e[t] = e; g_tile_m[t] = m << 7; t++; }
            s += (c + 127) & ~127;
        }
        for (; t < MAXTILES; t++) g_tile_e[t] = -1;
    }
}

__global__ void scatter_kernel() {
    int i = blockIdx.x * blockDim.x + threadIdx.x;
    if (i >= NROUTED) return;
    int t = i >> 1;
    int e = g_topk_idx[i];
    int pos = atomicAdd(&g_cursor[e], 1);
    g_perm[pos] = t;
    g_wgt[pos] = g_topk_w[i];
    g_entry_of[i] = pos;
}

// ---------------- gate+up MMA GEMM ----------------
// block M128 x N64, 8 warps 4Mx2N, warp 32x32 G+U, occ 2
// 3-buffer pipeline, ONE barrier per stage (wait -> bar -> issue(s+2) -> compute)
#define GU_AOFF  0
#define GU_GOFF  16384
#define GU_UOFF  24576
#define GU_STAGE 32768          // A 16KB + G 8KB + U 8KB
#define GU_SMEM  (3 * GU_STAGE) // 96KB

__global__ __launch_bounds__(256, 2) void gateup_mma() {
    extern __shared__ char sm[];
    uint32_t sb = smem_u32(sm);
    int tid = threadIdx.x, wid = tid >> 5, lane = tid & 31;

    int y = blockIdx.y;
    int e, m0, base;
    bool is_shared;
    if (y >= MAXTILES) {
        is_shared = true; m0 = (y - MAXTILES) << 7; base = SHB;
    } else {
        e = g_tile_e[y];
        if (e < 0) return;
        is_shared = false; m0 = g_tile_m[y]; base = g_offp[e];
    }
    int n0 = blockIdx.x * 64;

    const __half* WG = is_shared ? g_sg : g_wg + (size_t)e * IDIM * HDIM;
    const __half* WU = is_shared ? g_su : g_wu + (size_t)e * IDIM * HDIM;

    int lrowA = tid >> 1, kb0 = (tid & 1) * 4;
    uint32_t swoA[4];
#pragma unroll
    for (int j = 0; j < 4; j++)
        swoA[j] = lrowA * 128 + (((kb0 + j) ^ (lrowA & 7)) << 4);
    int tok = is_shared ? (m0 + lrowA) : g_perm[base + m0 + lrowA];
    const __half* pA = g_x16 + (size_t)tok * HDIM + kb0 * 8;

    int lrowB = tid >> 2, cb0 = tid & 3;
    uint32_t swoB[2];
    swoB[0] = lrowB * 128 + ((cb0 ^ (lrowB & 7)) << 4);
    swoB[1] = lrowB * 128 + (((cb0 + 4) ^ (lrowB & 7)) << 4);
    const __half* pG = WG + (size_t)(n0 + lrowB) * HDIM + cb0 * 8;
    const __half* pU = WU + (size_t)(n0 + lrowB) * HDIM + cb0 * 8;

    auto issue = [&](int s) {
        int k0 = s * 64;
        uint32_t bb = sb + (s % 3) * GU_STAGE;
#pragma unroll
        for (int j = 0; j < 4; j++)
            cpasync16(bb + GU_AOFF + swoA[j], pA + k0 + j * 8);
        cpasync16(bb + GU_GOFF + swoB[0], pG + k0);
        cpasync16(bb + GU_GOFF + swoB[1], pG + k0 + 32);
        cpasync16(bb + GU_UOFF + swoB[0], pU + k0);
        cpasync16(bb + GU_UOFF + swoB[1], pU + k0 + 32);
    };

    int warpM = (wid >> 1) * 32;
    int warpN = (wid & 1) * 32;
    int la = lane & 15, kh = lane >> 4, x7 = la & 7;
    uint32_t rowA[2], rowB[2];
#pragma unroll
    for (int mf = 0; mf < 2; mf++) rowA[mf] = (warpM + mf * 16 + la) * 128;
#pragma unroll
    for (int s2 = 0; s2 < 2; s2++) rowB[s2] = (warpN + s2 * 16 + la) * 128;

    float aG[2][4][4], aU[2][4][4];
#pragma unroll
    for (int mf = 0; mf < 2; mf++)
#pragma unroll
        for (int nf = 0; nf < 4; nf++)
#pragma unroll
            for (int q = 0; q < 4; q++) { aG[mf][nf][q] = 0.f; aU[mf][nf][q] = 0.f; }

    issue(0); CP_COMMIT();
    issue(1); CP_COMMIT();
    const int S = 16;
    for (int s = 0; s < S; s++) {
        if (s == S - 1) CP_WAIT0(); else CP_WAIT1();
        __syncthreads();
        if (s + 2 < S) { issue(s + 2); CP_COMMIT(); }
        uint32_t bb = sb + (s % 3) * GU_STAGE;
#pragma unroll
        for (int k16 = 0; k16 < 4; k16++) {
            uint32_t ko = (uint32_t)(((k16 * 2 + kh) ^ x7) << 4);
            uint32_t A[2][4];
#pragma unroll
            for (int mf = 0; mf < 2; mf++)
                ldsm4(A[mf], bb + GU_AOFF + rowA[mf] + ko);
            uint32_t G[2][4], U[2][4];
#pragma unroll
            for (int s2 = 0; s2 < 2; s2++) {
                ldsm4(G[s2], bb + GU_GOFF + rowB[s2] + ko);
                ldsm4(U[s2], bb + GU_UOFF + rowB[s2] + ko);
            }
#pragma unroll
            for (int mf = 0; mf < 2; mf++)
#pragma unroll
                for (int s2 = 0; s2 < 2; s2++)
#pragma unroll
                    for (int j = 0; j < 2; j++) {
                        int nf = s2 * 2 + j;
                        mma16816(aG[mf][nf], A[mf], G[s2][j], G[s2][2 + j]);
                        mma16816(aU[mf][nf], A[mf], U[s2][j], U[s2][2 + j]);
                    }
        }
    }

    // epilogue: hmid = silu(g)*u -> fp16
    int qr = lane >> 2, qc = (lane & 3) * 2;
#pragma unroll
    for (int mf = 0; mf < 2; mf++)
#pragma unroll
        for (int nf = 0; nf < 4; nf++) {
            int col = n0 + warpN + nf * 8 + qc;
            float* cg = aG[mf][nf];
            float* cu = aU[mf][nf];
            int r0 = m0 + warpM + mf * 16 + qr;
            float g0 = cg[0], g1 = cg[1], g2 = cg[2], g3 = cg[3];
            float v00 = (g0 / (1.f + expf(-g0))) * cu[0];
            float v01 = (g1 / (1.f + expf(-g1))) * cu[1];
            float v10 = (g2 / (1.f + expf(-g2))) * cu[2];
            float v11 = (g3 / (1.f + expf(-g3))) * cu[3];
            uint32_t p0 = pack2h(__float2half_rn(v00), __float2half_rn(v01));
            uint32_t p1 = pack2h(__float2half_rn(v10), __float2half_rn(v11));
            size_t o0 = (size_t)(base + r0) * IDIM + col;
            size_t o1 = o0 + (size_t)8 * IDIM;
            *(uint32_t*)(g_hm + o0) = p0;
            *(uint32_t*)(g_hm + o1) = p1;
        }
}

// ---------------- down MMA GEMM ----------------
// 3-buffer pipeline, one bar per stage; occ 2
#define DN_PART  16384
#define DN_STAGE (2 * DN_PART)   // A, B
#define DN_SMEM  (3 * DN_STAGE)  // 96KB

__global__ __launch_bounds__(256, 2) void down_mma() {
    extern __shared__ char sm[];
    uint32_t sb = smem_u32(sm);
    int tid = threadIdx.x, wid = tid >> 5, lane = tid & 31;

    int y = blockIdx.y;
    int e, m0, base;
    bool is_shared;
    if (y >= MAXTILES) {
        is_shared = true; m0 = (y - MAXTILES) << 7; base = SHB;
    } else {
        e = g_tile_e[y];
        if (e < 0) return;
        is_shared = false; m0 = g_tile_m[y]; base = g_offp[e];
    }
    int n0 = blockIdx.x * 128;

    const __half* WD = is_shared ? g_sd : g_wd + (size_t)e * HDIM * IDIM;

    int lrow = tid >> 1, kb0 = (tid & 1) * 4;
    uint32_t swo[4];
#pragma unroll
    for (int j = 0; j < 4; j++)
        swo[j] = lrow * 128 + (((kb0 + j) ^ (lrow & 7)) << 4);
    const __half* pA = g_hm + (size_t)(base + m0 + lrow) * IDIM + kb0 * 8;
    const __half* pB = WD + (size_t)(n0 + lrow) * IDIM + kb0 * 8;

    auto issue = [&](int s) {
        int k0 = s * 64;
        uint32_t bb = sb + (s % 3) * DN_STAGE;
#pragma unroll
        for (int j = 0; j < 4; j++) {
            cpasync16(bb + 0 * DN_PART + swo[j], pA + k0 + j * 8);
            cpasync16(bb + 1 * DN_PART + swo[j], pB + k0 + j * 8);
        }
    };

    int warpM = (wid & 1) * 64;
    int warpN = (wid >> 1) * 32;
    int la = lane & 15, kh = lane >> 4, x7 = la & 7;
    uint32_t rowA[4], rowB[2];
#pragma unroll
    for (int mf = 0; mf < 4; mf++) rowA[mf] = (warpM + mf * 16 + la) * 128;
#pragma unroll
    for (int s2 = 0; s2 < 2; s2++) rowB[s2] = (warpN + s2 * 16 + la) * 128;

    float acc[4][4][4];
#pragma unroll
    for (int mf = 0; mf < 4; mf++)
#pragma unroll
        for (int nf = 0; nf < 4; nf++)
#pragma unroll
            for (int q = 0; q < 4; q++) acc[mf][nf][q] = 0.f;

    const int S = IDIM / 64;   // 43
    issue(0); CP_COMMIT();
    issue(1); CP_COMMIT();
    for (int s = 0; s < S; s++) {
        if (s == S - 1) CP_WAIT0(); else CP_WAIT1();
        __syncthreads();
        if (s + 2 < S) { issue(s + 2); CP_COMMIT(); }
        uint32_t bb = sb + (s % 3) * DN_STAGE;
#pragma unroll
        for (int k16 = 0; k16 < 4; k16++) {
            uint32_t ko = (uint32_t)(((k16 * 2 + kh) ^ x7) << 4);
            uint32_t A[4][4];
#pragma unroll
            for (int mf = 0; mf < 4; mf++)
                ldsm4(A[mf], bb + 0 * DN_PART + rowA[mf] + ko);
            uint32_t B[2][4];
#pragma unroll
            for (int s2 = 0; s2 < 2; s2++)
                ldsm4(B[s2], bb + 1 * DN_PART + rowB[s2] + ko);
#pragma unroll
            for (int mf = 0; mf < 4; mf++)
#pragma unroll
                for (int s2 = 0; s2 < 2; s2++)
#pragma unroll
                    for (int j = 0; j < 2; j++) {
                        int nf = s2 * 2 + j;
                        mma16816(acc[mf][nf], A[mf], B[s2][j], B[s2][2 + j]);
                    }
        }
    }

    int qr = lane >> 2, qc = (lane & 3) * 2;
#pragma unroll
    for (int mf = 0; mf < 4; mf++) {
        int r0 = m0 + warpM + mf * 16 + qr;
        float w0 = is_shared ? 1.f : g_wgt[base + r0];
        float w1 = is_shared ? 1.f : g_wgt[base + r0 + 8];
#pragma unroll
        for (int nf = 0; nf < 4; nf++) {
            int col = n0 + warpN + nf * 8 + qc;
            float* c = acc[mf][nf];
            size_t o0 = (size_t)(base + r0) * HDIM + col;
            size_t o1 = o0 + (size_t)8 * HDIM;
            float2 v0 = make_float2(c[0] * w0, c[1] * w0);
            float2 v1 = make_float2(c[2] * w1, c[3] * w1);
            *(float2*)(g_eo + o0) = v0;
            *(float2*)(g_eo + o1) = v1;
        }
    }
}

// ---------------- combine ----------------
__global__ void combine_kernel(float* __restrict__ out) {
    int idx = blockIdx.x * blockDim.x + threadIdx.x;
    const int HC = HDIM / 4;
    if (idx >= NT * HC) return;
    int t = idx / HC;
    int c = idx - t * HC;
    const float4* eo4 = (const float4*)g_eo;
    int e1 = g_entry_of[2 * t + 0];
    int e2 = g_entry_of[2 * t + 1];
    float4 a = eo4[(size_t)e1 * HC + c];
    float4 b = eo4[(size_t)e2 * HC + c];
    float4 s = eo4[(size_t)(SHB + t) * HC + c];
    float4 r;
    r.x = a.x + b.x + s.x;
    r.y = a.y + b.y + s.y;
    r.z = a.z + b.z + s.z;
    r.w = a.w + b.w + s.w;
    ((float4*)out)[idx] = r;
}

// ---------------- launch ----------------
extern "C" void kernel_launch(void* const* d_in, const int* in_sizes, int n_in,
                              void* d_out, int out_size) {
    const float* x       = (const float*)d_in[0];
    const float* gate_w  = (const float*)d_in[1];
    const float* w_gate  = (const float*)d_in[2];
    const float* w_up    = (const float*)d_in[3];
    const float* w_down  = (const float*)d_in[4];
    const float* ws_gate = (const float*)d_in[5];
    const float* ws_up   = (const float*)d_in[6];
    const float* ws_down = (const float*)d_in[7];
    float* out = (float*)d_out;

    cudaFuncSetAttribute(gateup_mma, cudaFuncAttributeMaxDynamicSharedMemorySize, GU_SMEM);
    cudaFuncSetAttribute(down_mma,   cudaFuncAttributeMaxDynamicSharedMemorySize, DN_SMEM);

    __half *x16, *wg, *wu, *wd, *sg, *su, *sd;
    cudaGetSymbolAddress((void**)&x16, g_x16);
    cudaGetSymbolAddress((void**)&wg, g_wg); cudaGetSymbolAddress((void**)&wu, g_wu);
    cudaGetSymbolAddress((void**)&wd, g_wd);
    cudaGetSymbolAddress((void**)&sg, g_sg); cudaGetSymbolAddress((void**)&su, g_su);
    cudaGetSymbolAddress((void**)&sd, g_sd);

    ConvArgs ca;
    ca.src[0] = x;       ca.dst[0] = x16;
    ca.src[1] = w_gate;  ca.dst[1] = wg;
    ca.src[2] = w_up;    ca.dst[2] = wu;
    ca.src[3] = w_down;  ca.dst[3] = wd;
    ca.src[4] = ws_gate; ca.dst[4] = sg;
    ca.src[5] = ws_up;   ca.dst[5] = su;
    ca.src[6] = ws_down; ca.dst[6] = sd;
    int sz8[7] = {
        NT * HDIM / 8,
        NE * IDIM * HDIM / 8, NE * IDIM * HDIM / 8, NE * IDIM * HDIM / 8,
        IDIM * HDIM / 8, IDIM * HDIM / 8, IDIM * HDIM / 8
    };
    ca.cum[0] = 0;
    for (int i = 0; i < 7; i++) ca.cum[i + 1] = ca.cum[i] + sz8[i];
    int total = ca.cum[7];

    int conv_blocks = (total + 255) / 256;
    conv_gate_kernel<<<GATE_BLOCKS + conv_blocks, 256>>>(ca, x, gate_w);
    scan_kernel<<<1, 256>>>();
    scatter_kernel<<<(NROUTED + 255) / 256, 256>>>();

    gateup_mma<<<dim3(IDIM / 64, MAXTILES + NT / 128, 1), 256, GU_SMEM>>>();
    down_mma<<<dim3(HDIM / 128, MAXTILES + NT / 128, 1), 256, DN_SMEM>>>();
    combine_kernel<<<(NT * (HDIM / 4) + 255) / 256, 256>>>(out);
}